// round 6
// baseline (speedup 1.0000x reference)
#include <cuda_runtime.h>
#include <cstdint>
#include <cstddef>

#define B_   2
#define T_   2048
#define C_   1024
#define NH_  16
#define HD_  64
#define C3_  3072
#define ROWS_ 4096

// ---------------------------------------------------------------------------
// Scratch (__device__ globals; allocation-free rule)
// ---------------------------------------------------------------------------
__device__ float g_qkv[(size_t)ROWS_ * C3_];   // 48 MB, tf32-rounded by gemm epilogue
__device__ float g_y[(size_t)ROWS_ * C_];      // 16 MB, tf32-rounded by attn epilogue
__device__ float g_xr[(size_t)ROWS_ * C_];     // 16 MB pre-rounded x
__device__ float g_war[(size_t)C_ * C3_];      // 12 MB pre-rounded w_attn
__device__ float g_wpr[(size_t)C_ * C_];       //  4 MB pre-rounded w_proj

// ---------------------------------------------------------------------------
// Helpers (sm_80-era ISA only: harness ptxas target is sm_103 without 'a',
// so tcgen05/TMEM instructions are unavailable)
// ---------------------------------------------------------------------------
__device__ __forceinline__ float f2tf32(float x) {
    uint32_t u;
    asm("cvt.rna.tf32.f32 %0, %1;" : "=r"(u) : "f"(x));
    return __uint_as_float(u);
}

__device__ __forceinline__ void mma_tf32(float d[4], const uint32_t a[4], const uint32_t b[2]) {
    asm volatile(
        "mma.sync.aligned.m16n8k8.row.col.f32.tf32.tf32.f32 "
        "{%0,%1,%2,%3}, {%4,%5,%6,%7}, {%8,%9}, {%0,%1,%2,%3};\n"
        : "+f"(d[0]), "+f"(d[1]), "+f"(d[2]), "+f"(d[3])
        : "r"(a[0]), "r"(a[1]), "r"(a[2]), "r"(a[3]), "r"(b[0]), "r"(b[1]));
}

__device__ __forceinline__ void cp_async16(void* smem_dst, const void* gsrc) {
    uint32_t s = (uint32_t)__cvta_generic_to_shared(smem_dst);
    asm volatile("cp.async.ca.shared.global [%0], [%1], 16;\n" :: "r"(s), "l"(gsrc));
}
#define CP_COMMIT asm volatile("cp.async.commit_group;\n" ::: "memory")
#define CP_WAIT_1 asm volatile("cp.async.wait_group 1;\n" ::: "memory")
#define CP_WAIT_0 asm volatile("cp.async.wait_group 0;\n" ::: "memory")

// ---------------------------------------------------------------------------
// Elementwise tf32 pre-round
// ---------------------------------------------------------------------------
__global__ void round_tf32_kernel(const float4* __restrict__ in, float4* __restrict__ out, int n4)
{
    int i = blockIdx.x * 256 + threadIdx.x;
    if (i < n4) {
        float4 v = in[i];
        v.x = f2tf32(v.x); v.y = f2tf32(v.y);
        v.z = f2tf32(v.z); v.w = f2tf32(v.w);
        out[i] = v;
    }
}

// ---------------------------------------------------------------------------
// TF32 GEMM, 3-stage cp.async pipeline, one __syncthreads per k-iter.
// C[M,N] = A[M,K]*B[K,N], row-major, inputs already tf32-rounded.
// Block 128x128x32, 256 threads, warp grid 4(m)x2(n), warp tile 32x64.
// ---------------------------------------------------------------------------
#define GBM 128
#define GBN 128
#define GBK 32
#define ASTR 36     // 4 mod 32 -> conflict-free a-frag reads
#define BSTR 136    // 8 mod 32 -> conflict-free b-frag reads
#define A_BUF (GBM * ASTR)                        // 4608 floats
#define B_BUF (GBK * BSTR)                        // 4352 floats
#define STG_F (A_BUF + B_BUF)                     // 8960 floats / stage
#define GEMM_SMEM (3 * STG_F * 4)                 // 107520 B (2 CTAs/SM)

template<bool ROUND_OUT>
__global__ __launch_bounds__(256, 2)
void gemm_tf32_cp(const float* __restrict__ A, const float* __restrict__ Bm,
                  float* __restrict__ Cm, int M, int N, int K)
{
    extern __shared__ float sm[];
    const int tid  = threadIdx.x;
    const int lane = tid & 31;
    const int warp = tid >> 5;
    const int wm   = warp & 3;
    const int wn   = warp >> 2;
    const int g    = lane >> 2;
    const int tg   = lane & 3;
    const int bm   = blockIdx.y * GBM;
    const int bn   = blockIdx.x * GBN;

    float acc[2][8][4];
    #pragma unroll
    for (int i = 0; i < 2; i++)
        #pragma unroll
        for (int j = 0; j < 8; j++)
            #pragma unroll
            for (int k = 0; k < 4; k++) acc[i][j][k] = 0.f;

    // hoisted fragment smem offsets
    const int a_off0 = (wm * 32 + g) * ASTR + tg;        // + kk*8 ; +8*ASTR ; +4
    const int b_off0 = tg * BSTR + wn * 64 + g;          // + kk*8*BSTR ; +4*BSTR ; +nt*8

    auto load_stage = [&](int kt, int s) {
        float* As = sm + s * STG_F;
        float* Bs = As + A_BUF;
        #pragma unroll
        for (int p = 0; p < 4; p++) {
            int idx = tid + p * 256;
            int r = idx >> 3, c = (idx & 7) * 4;
            cp_async16(&As[r * ASTR + c], &A[(size_t)(bm + r) * K + kt * GBK + c]);
        }
        #pragma unroll
        for (int p = 0; p < 4; p++) {
            int idx = tid + p * 256;
            int r = idx >> 5, c = (idx & 31) * 4;
            cp_async16(&Bs[r * BSTR + c], &Bm[(size_t)(kt * GBK + r) * N + bn + c]);
        }
    };

    const int nk = K / GBK;
    load_stage(0, 0); CP_COMMIT;
    load_stage(1, 1); CP_COMMIT;

    for (int kt = 0; kt < nk; kt++) {
        const int cur = kt % 3;
        if (kt + 1 < nk) { CP_WAIT_1; } else { CP_WAIT_0; }
        __syncthreads();
        if (kt + 2 < nk) { load_stage(kt + 2, (kt + 2) % 3); CP_COMMIT; }

        const float* As = sm + cur * STG_F;
        const float* Bs = As + A_BUF;

        #pragma unroll
        for (int kk = 0; kk < 4; kk++) {
            uint32_t af[2][4], bf[8][2];
            #pragma unroll
            for (int mt = 0; mt < 2; mt++) {
                const int o = a_off0 + mt * 16 * ASTR + kk * 8;
                af[mt][0] = __float_as_uint(As[o]);
                af[mt][1] = __float_as_uint(As[o + 8 * ASTR]);
                af[mt][2] = __float_as_uint(As[o + 4]);
                af[mt][3] = __float_as_uint(As[o + 8 * ASTR + 4]);
            }
            #pragma unroll
            for (int nt = 0; nt < 8; nt++) {
                const int o = b_off0 + kk * 8 * BSTR + nt * 8;
                bf[nt][0] = __float_as_uint(Bs[o]);
                bf[nt][1] = __float_as_uint(Bs[o + 4 * BSTR]);
            }
            #pragma unroll
            for (int mt = 0; mt < 2; mt++)
                #pragma unroll
                for (int nt = 0; nt < 8; nt++)
                    mma_tf32(acc[mt][nt], af[mt], bf[nt]);
        }
    }

    #pragma unroll
    for (int mt = 0; mt < 2; mt++) {
        const int r0 = bm + wm * 32 + mt * 16 + g;
        #pragma unroll
        for (int nt = 0; nt < 8; nt++) {
            const int cc = bn + wn * 64 + nt * 8 + 2 * tg;
            float2 v0, v1;
            if (ROUND_OUT) {
                v0 = make_float2(f2tf32(acc[mt][nt][0]), f2tf32(acc[mt][nt][1]));
                v1 = make_float2(f2tf32(acc[mt][nt][2]), f2tf32(acc[mt][nt][3]));
            } else {
                v0 = make_float2(acc[mt][nt][0], acc[mt][nt][1]);
                v1 = make_float2(acc[mt][nt][2], acc[mt][nt][3]);
            }
            *(float2*)&Cm[(size_t)r0 * N + cc]       = v0;
            *(float2*)&Cm[(size_t)(r0 + 8) * N + cc] = v1;
        }
    }
}

// ---------------------------------------------------------------------------
// Flash attention, TF32 MMA, cp.async double-buffered KV.
// Softmax in base-2 domain: log2(e) folded into the Q scale, exp2f only.
// One block per (q-tile of 128, b*h). 8 warps x 16 q-rows; KV tile 64.
// ---------------------------------------------------------------------------
#define KV_BUF (64 * 68)
#define PS_OFF (4 * KV_BUF)
#define ATT_SMEM ((4 * KV_BUF + 8 * 16 * 68) * 4)   // 104448 B

__global__ __launch_bounds__(256, 2)
void attn_kernel(const float* __restrict__ qkv, float* __restrict__ y)
{
    extern __shared__ float sm[];
    const int tid  = threadIdx.x;
    const int lane = tid & 31;
    const int warp = tid >> 5;
    const int g    = lane >> 2;
    const int tg   = lane & 3;

    const int qt = gridDim.x - 1 - blockIdx.x;   // heavy tiles first
    const int bh = blockIdx.y;
    const int b  = bh >> 4;
    const int h  = bh & 15;

    const float* base = qkv + (size_t)b * T_ * C3_;
    const int qcol = h * HD_;
    const int kcol = C_ + h * HD_;
    const int vcol = 2 * C_ + h * HD_;

    auto load_kv = [&](int j, int buf) {
        float* Ksb = sm + buf * KV_BUF;
        float* Vsb = sm + 2 * KV_BUF + buf * KV_BUF;
        #pragma unroll
        for (int p = 0; p < 4; p++) {
            int idx = tid + p * 256;
            int r = idx >> 4, c = (idx & 15) * 4;
            size_t grow = (size_t)(j * 64 + r) * C3_;
            cp_async16(&Ksb[r * 68 + c], &base[grow + kcol + c]);
            cp_async16(&Vsb[r * 68 + c], &base[grow + vcol + c]);
        }
    };

    const int jend = 2 * qt + 1;
    load_kv(0, 0); CP_COMMIT;

    // Q a-fragments scaled by (1/sqrt(HD)) * log2(e) -> scores in base-2 domain
    uint32_t qf[8][4];
    {
        const int r0 = qt * 128 + warp * 16 + g;
        const float sc = 0.125f * 1.4426950408889634f;
        #pragma unroll
        for (int ks = 0; ks < 8; ks++) {
            const int c = qcol + ks * 8 + tg;
            qf[ks][0] = __float_as_uint(f2tf32(base[(size_t)r0 * C3_ + c] * sc));
            qf[ks][1] = __float_as_uint(f2tf32(base[(size_t)(r0 + 8) * C3_ + c] * sc));
            qf[ks][2] = __float_as_uint(f2tf32(base[(size_t)r0 * C3_ + c + 4] * sc));
            qf[ks][3] = __float_as_uint(f2tf32(base[(size_t)(r0 + 8) * C3_ + c + 4] * sc));
        }
    }

    float o[8][4];
    #pragma unroll
    for (int i = 0; i < 8; i++)
        #pragma unroll
        for (int jj = 0; jj < 4; jj++) o[i][jj] = 0.f;
    float m0 = -INFINITY, m1 = -INFINITY, l0 = 0.f, l1 = 0.f;

    float* Pw = sm + PS_OFF + warp * 16 * 68;

    for (int j = 0; j <= jend; j++) {
        const int cur = j & 1;
        if (j < jend) { load_kv(j + 1, cur ^ 1); CP_COMMIT; CP_WAIT_1; }
        else          { CP_WAIT_0; }
        __syncthreads();

        const float* Ksb = sm + cur * KV_BUF;
        const float* Vsb = sm + 2 * KV_BUF + cur * KV_BUF;

        // S = (Q*scale) @ K^T   (base-2 logits)
        float s[8][4];
        #pragma unroll
        for (int nt = 0; nt < 8; nt++)
            #pragma unroll
            for (int k4 = 0; k4 < 4; k4++) s[nt][k4] = 0.f;

        #pragma unroll
        for (int ks = 0; ks < 8; ks++) {
            #pragma unroll
            for (int nt = 0; nt < 8; nt++) {
                uint32_t bf[2];
                bf[0] = __float_as_uint(Ksb[(nt * 8 + g) * 68 + ks * 8 + tg]);
                bf[1] = __float_as_uint(Ksb[(nt * 8 + g) * 68 + ks * 8 + tg + 4]);
                mma_tf32(s[nt], qf[ks], bf);
            }
        }

        if (j >= 2 * qt) {   // causal mask, diagonal-overlapping tiles only
            const int rg0 = qt * 128 + warp * 16 + g;
            const int rg1 = rg0 + 8;
            #pragma unroll
            for (int nt = 0; nt < 8; nt++) {
                const int c0 = j * 64 + nt * 8 + 2 * tg;
                if (c0     > rg0) s[nt][0] = -1e30f;
                if (c0 + 1 > rg0) s[nt][1] = -1e30f;
                if (c0     > rg1) s[nt][2] = -1e30f;
                if (c0 + 1 > rg1) s[nt][3] = -1e30f;
            }
        }

        // Online softmax, base-2 (row g -> s[.][0,1], row g+8 -> s[.][2,3])
        float mt0 = -INFINITY, mt1 = -INFINITY;
        #pragma unroll
        for (int nt = 0; nt < 8; nt++) {
            mt0 = fmaxf(mt0, fmaxf(s[nt][0], s[nt][1]));
            mt1 = fmaxf(mt1, fmaxf(s[nt][2], s[nt][3]));
        }
        mt0 = fmaxf(mt0, __shfl_xor_sync(0xffffffffu, mt0, 1));
        mt0 = fmaxf(mt0, __shfl_xor_sync(0xffffffffu, mt0, 2));
        mt1 = fmaxf(mt1, __shfl_xor_sync(0xffffffffu, mt1, 1));
        mt1 = fmaxf(mt1, __shfl_xor_sync(0xffffffffu, mt1, 2));

        const float mn0 = fmaxf(m0, mt0), mn1 = fmaxf(m1, mt1);
        const float f0 = exp2f(m0 - mn0), f1 = exp2f(m1 - mn1);

        float ls0 = 0.f, ls1 = 0.f;
        float* prow0 = Pw + g * 68;
        float* prow1 = prow0 + 8 * 68;
        #pragma unroll
        for (int nt = 0; nt < 8; nt++) {
            const float p0 = exp2f(s[nt][0] - mn0);
            const float p1 = exp2f(s[nt][1] - mn0);
            const float p2 = exp2f(s[nt][2] - mn1);
            const float p3 = exp2f(s[nt][3] - mn1);
            ls0 += p0 + p1; ls1 += p2 + p3;
            const int c = nt * 8 + 2 * tg;
            *(float2*)&prow0[c] = make_float2(f2tf32(p0), f2tf32(p1));
            *(float2*)&prow1[c] = make_float2(f2tf32(p2), f2tf32(p3));
        }
        ls0 += __shfl_xor_sync(0xffffffffu, ls0, 1);
        ls0 += __shfl_xor_sync(0xffffffffu, ls0, 2);
        ls1 += __shfl_xor_sync(0xffffffffu, ls1, 1);
        ls1 += __shfl_xor_sync(0xffffffffu, ls1, 2);

        l0 = l0 * f0 + ls0;
        l1 = l1 * f1 + ls1;
        m0 = mn0; m1 = mn1;

        #pragma unroll
        for (int nt = 0; nt < 8; nt++) {
            o[nt][0] *= f0; o[nt][1] *= f0;
            o[nt][2] *= f1; o[nt][3] *= f1;
        }
        __syncwarp();   // per-warp P writes -> a-frag reads

        // O += P @ V   (V untransposed [kv][hd])
        #pragma unroll
        for (int ks = 0; ks < 8; ks++) {
            uint32_t af[4];
            af[0] = __float_as_uint(Pw[g * 68 + ks * 8 + tg]);
            af[1] = __float_as_uint(Pw[(g + 8) * 68 + ks * 8 + tg]);
            af[2] = __float_as_uint(Pw[g * 68 + ks * 8 + tg + 4]);
            af[3] = __float_as_uint(Pw[(g + 8) * 68 + ks * 8 + tg + 4]);
            #pragma unroll
            for (int nt = 0; nt < 8; nt++) {
                uint32_t bf[2];
                bf[0] = __float_as_uint(Vsb[(ks * 8 + tg) * 68 + nt * 8 + g]);
                bf[1] = __float_as_uint(Vsb[(ks * 8 + tg + 4) * 68 + nt * 8 + g]);
                mma_tf32(o[nt], af, bf);
            }
        }
        __syncthreads();   // buf[cur] reads done before refill at j+2
    }

    const float i0 = 1.f / l0, i1 = 1.f / l1;
    const int r0 = b * T_ + qt * 128 + warp * 16 + g;
    #pragma unroll
    for (int nt = 0; nt < 8; nt++) {
        const int c = h * HD_ + nt * 8 + 2 * tg;
        *(float2*)&y[(size_t)r0 * C_ + c] =
            make_float2(f2tf32(o[nt][0] * i0), f2tf32(o[nt][1] * i0));
        *(float2*)&y[(size_t)(r0 + 8) * C_ + c] =
            make_float2(f2tf32(o[nt][2] * i1), f2tf32(o[nt][3] * i1));
    }
}

// ---------------------------------------------------------------------------
// Launch chain
// ---------------------------------------------------------------------------
extern "C" void kernel_launch(void* const* d_in, const int* in_sizes, int n_in,
                              void* d_out, int out_size)
{
    (void)in_sizes; (void)n_in; (void)out_size;
    const float* x      = (const float*)d_in[0];
    const float* w_attn = (const float*)d_in[1];
    const float* w_proj = (const float*)d_in[2];
    float* out = (float*)d_out;

    float *qkv, *y, *xr, *war, *wpr;
    cudaGetSymbolAddress((void**)&qkv, g_qkv);
    cudaGetSymbolAddress((void**)&y,   g_y);
    cudaGetSymbolAddress((void**)&xr,  g_xr);
    cudaGetSymbolAddress((void**)&war, g_war);
    cudaGetSymbolAddress((void**)&wpr, g_wpr);

    cudaFuncSetAttribute(gemm_tf32_cp<true>,  cudaFuncAttributeMaxDynamicSharedMemorySize, GEMM_SMEM);
    cudaFuncSetAttribute(gemm_tf32_cp<false>, cudaFuncAttributeMaxDynamicSharedMemorySize, GEMM_SMEM);
    cudaFuncSetAttribute(attn_kernel,         cudaFuncAttributeMaxDynamicSharedMemorySize, ATT_SMEM);

    const int n4x = ROWS_ * C_ / 4;
    const int n4a = C_ * C3_ / 4;
    const int n4p = C_ * C_ / 4;
    round_tf32_kernel<<<(n4x + 255) / 256, 256>>>((const float4*)x,      (float4*)xr,  n4x);
    round_tf32_kernel<<<(n4a + 255) / 256, 256>>>((const float4*)w_attn, (float4*)war, n4a);
    round_tf32_kernel<<<(n4p + 255) / 256, 256>>>((const float4*)w_proj, (float4*)wpr, n4p);

    gemm_tf32_cp<true><<<dim3(C3_ / GBN, ROWS_ / GBM), 256, GEMM_SMEM>>>(xr, war, qkv, ROWS_, C3_, C_);
    attn_kernel<<<dim3(T_ / 128, B_ * NH_), 256, ATT_SMEM>>>(qkv, y);
    gemm_tf32_cp<false><<<dim3(C_ / GBN, ROWS_ / GBM), 256, GEMM_SMEM>>>(y, wpr, out, ROWS_, C_, C_);
}

// round 7
// speedup vs baseline: 2.1430x; 2.1430x over previous
#include <cuda_runtime.h>
#include <cuda_fp16.h>
#include <cstdint>
#include <cstddef>

#define B_   2
#define T_   2048
#define C_   1024
#define NH_  16
#define HD_  64
#define C3_  3072
#define ROWS_ 4096

// ---------------------------------------------------------------------------
// Scratch (__device__ globals; allocation-free rule). All intermediates fp16.
// ---------------------------------------------------------------------------
__device__ __half g_qkv[(size_t)ROWS_ * C3_];   // 24 MB
__device__ __half g_y[(size_t)ROWS_ * C_];      //  8 MB
__device__ __half g_xh[(size_t)ROWS_ * C_];     //  8 MB  x -> half
__device__ __half g_wah[(size_t)C_ * C3_];      //  6 MB  w_attn -> half
__device__ __half g_wph[(size_t)C_ * C_];       //  2 MB  w_proj -> half

// ---------------------------------------------------------------------------
// Helpers (sm_80-era ISA only; harness ptxas target lacks the 'a' suffix)
// ---------------------------------------------------------------------------
__device__ __forceinline__ void cp_async16(void* smem_dst, const void* gsrc) {
    uint32_t s = (uint32_t)__cvta_generic_to_shared(smem_dst);
    asm volatile("cp.async.ca.shared.global [%0], [%1], 16;\n" :: "r"(s), "l"(gsrc));
}
#define CP_COMMIT asm volatile("cp.async.commit_group;\n" ::: "memory")
#define CP_WAIT_1 asm volatile("cp.async.wait_group 1;\n" ::: "memory")
#define CP_WAIT_0 asm volatile("cp.async.wait_group 0;\n" ::: "memory")

// SW128 swizzle on byte offsets within a tile of 128-byte rows
#define SWZ128(off) ((off) ^ (((off) >> 3) & 0x70))

__device__ __forceinline__ void ldsm4(uint32_t r[4], uint32_t addr) {
    asm volatile("ldmatrix.sync.aligned.m8n8.x4.shared.b16 {%0,%1,%2,%3}, [%4];"
        : "=r"(r[0]), "=r"(r[1]), "=r"(r[2]), "=r"(r[3]) : "r"(addr));
}
__device__ __forceinline__ void ldsm4t(uint32_t& r0, uint32_t& r1, uint32_t& r2, uint32_t& r3,
                                       uint32_t addr) {
    asm volatile("ldmatrix.sync.aligned.m8n8.x4.trans.shared.b16 {%0,%1,%2,%3}, [%4];"
        : "=r"(r0), "=r"(r1), "=r"(r2), "=r"(r3) : "r"(addr));
}

__device__ __forceinline__ void mma_f16(float d[4], const uint32_t a[4], const uint32_t b[2]) {
    asm volatile(
        "mma.sync.aligned.m16n8k16.row.col.f32.f16.f16.f32 "
        "{%0,%1,%2,%3}, {%4,%5,%6,%7}, {%8,%9}, {%0,%1,%2,%3};\n"
        : "+f"(d[0]), "+f"(d[1]), "+f"(d[2]), "+f"(d[3])
        : "r"(a[0]), "r"(a[1]), "r"(a[2]), "r"(a[3]), "r"(b[0]), "r"(b[1]));
}

// ---------------------------------------------------------------------------
// fp32 -> fp16 convert
// ---------------------------------------------------------------------------
__global__ void to_half_kernel(const float4* __restrict__ in, uint2* __restrict__ out, int n4)
{
    int i = blockIdx.x * 256 + threadIdx.x;
    if (i < n4) {
        float4 v = in[i];
        __half2 a = __floats2half2_rn(v.x, v.y);
        __half2 b = __floats2half2_rn(v.z, v.w);
        out[i] = make_uint2(*(uint32_t*)&a, *(uint32_t*)&b);
    }
}

// ---------------------------------------------------------------------------
// fp16 GEMM: C[M,N] = A[M,K] * B[K,N]  (A,B half; C half or float)
// Block 128x128x64, 256 threads, warp grid 4(m)x2(n), warp tile 32x64.
// ldmatrix + m16n8k16, SW128-style swizzled smem, 2-stage cp.async.
// ---------------------------------------------------------------------------
#define BM 128
#define BN 128
#define BK 64
#define A_ST_BYTES (BM * 128)                 // rows of 64 halves = 128 B
#define B_ST_BYTES (BK * 256)                 // rows of 128 halves = 256 B
#define STG_BYTES (A_ST_BYTES + B_ST_BYTES)   // 32768
#define GEMM_SMEM (2 * STG_BYTES)             // 65536

template<bool OUT_HALF>
__global__ __launch_bounds__(256, 2)
void gemm_f16(const __half* __restrict__ A, const __half* __restrict__ Bm,
              void* __restrict__ Cv, int M, int N, int K)
{
    extern __shared__ char smc[];
    const uint32_t sbase = (uint32_t)__cvta_generic_to_shared(smc);
    const int tid  = threadIdx.x;
    const int lane = tid & 31;
    const int warp = tid >> 5;
    const int wm   = warp & 3;
    const int wn   = warp >> 2;
    const int g    = lane >> 2;
    const int tg   = lane & 3;
    const int bm   = blockIdx.y * BM;
    const int bn   = blockIdx.x * BN;

    float acc[2][8][4];
    #pragma unroll
    for (int i = 0; i < 2; i++)
        #pragma unroll
        for (int j = 0; j < 8; j++)
            #pragma unroll
            for (int k = 0; k < 4; k++) acc[i][j][k] = 0.f;

    auto load_stage = [&](int kt, int s) {
        char* As = smc + s * STG_BYTES;
        char* Bs = As + A_ST_BYTES;
        #pragma unroll
        for (int p = 0; p < 4; p++) {        // A: 128 rows x 8 chunks
            int idx = tid + p * 256;
            int r = idx >> 3, c = idx & 7;
            cp_async16(As + SWZ128(r * 128 + c * 16),
                       A + (size_t)(bm + r) * K + kt * BK + c * 8);
        }
        #pragma unroll
        for (int p = 0; p < 4; p++) {        // B: 64 rows x 16 chunks (256B rows)
            int idx = tid + p * 256;
            int r = idx >> 4, c = idx & 15;
            cp_async16(Bs + r * 256 + ((c ^ (r & 7)) * 16),
                       Bm + (size_t)(kt * BK + r) * N + bn + c * 8);
        }
    };

    const int nk = K / BK;
    load_stage(0, 0); CP_COMMIT;

    for (int kt = 0; kt < nk; kt++) {
        const int cur = kt & 1;
        if (kt + 1 < nk) { load_stage(kt + 1, cur ^ 1); CP_COMMIT; CP_WAIT_1; }
        else             { CP_WAIT_0; }
        __syncthreads();

        const uint32_t aS = sbase + cur * STG_BYTES;
        const uint32_t bS = aS + A_ST_BYTES;

        #pragma unroll
        for (int ks = 0; ks < 4; ks++) {
            uint32_t af[2][4];
            #pragma unroll
            for (int mt = 0; mt < 2; mt++) {
                const int row = wm * 32 + mt * 16 + (lane & 15);
                const int ch  = ks * 2 + (lane >> 4);
                ldsm4(af[mt], aS + SWZ128(row * 128 + ch * 16));
            }
            uint32_t bf[8][2];
            #pragma unroll
            for (int pr = 0; pr < 4; pr++) {
                const int row = ks * 16 + (lane & 7) + (lane & 8);
                const int ch  = wn * 8 + pr * 2 + (lane >> 4);
                uint32_t r0, r1, r2, r3;
                ldsm4t(r0, r1, r2, r3, bS + row * 256 + ((ch ^ (row & 7)) * 16));
                bf[pr * 2][0] = r0;     bf[pr * 2][1] = r1;
                bf[pr * 2 + 1][0] = r2; bf[pr * 2 + 1][1] = r3;
            }
            #pragma unroll
            for (int mt = 0; mt < 2; mt++)
                #pragma unroll
                for (int nt = 0; nt < 8; nt++)
                    mma_f16(acc[mt][nt], af[mt], bf[nt]);
        }
        __syncthreads();
    }

    // Epilogue: c0,c1 -> (row g, cols 2tg,2tg+1); c2,c3 -> row g+8
    #pragma unroll
    for (int mt = 0; mt < 2; mt++) {
        const int r0 = bm + wm * 32 + mt * 16 + g;
        #pragma unroll
        for (int nt = 0; nt < 8; nt++) {
            const int cc = bn + wn * 64 + nt * 8 + 2 * tg;
            if (OUT_HALF) {
                __half* Ch = (__half*)Cv;
                __half2 v0 = __floats2half2_rn(acc[mt][nt][0], acc[mt][nt][1]);
                __half2 v1 = __floats2half2_rn(acc[mt][nt][2], acc[mt][nt][3]);
                *(__half2*)&Ch[(size_t)r0 * N + cc]       = v0;
                *(__half2*)&Ch[(size_t)(r0 + 8) * N + cc] = v1;
            } else {
                float* Cf = (float*)Cv;
                *(float2*)&Cf[(size_t)r0 * N + cc]       = make_float2(acc[mt][nt][0], acc[mt][nt][1]);
                *(float2*)&Cf[(size_t)(r0 + 8) * N + cc] = make_float2(acc[mt][nt][2], acc[mt][nt][3]);
            }
        }
    }
}

// ---------------------------------------------------------------------------
// Flash attention, fp16 MMA. One block per (q-tile of 128, b*h).
// 8 warps x 16 q-rows; KV tile 64; HD=64. Softmax fp32, base-2.
// smem (bytes): Q[0,16K) K[16K,32K) x2  V[32K,48K) x2  P[48K,64K)
// ---------------------------------------------------------------------------
#define Q_OFF 0
#define K_OFF 16384
#define V_OFF 32768
#define P_OFF 49152
#define ATT_SMEM 65536

__global__ __launch_bounds__(256, 2)
void attn_kernel(const __half* __restrict__ qkv, __half* __restrict__ y)
{
    extern __shared__ char smc[];
    const uint32_t sbase = (uint32_t)__cvta_generic_to_shared(smc);
    const int tid  = threadIdx.x;
    const int lane = tid & 31;
    const int warp = tid >> 5;
    const int g    = lane >> 2;
    const int tg   = lane & 3;

    const int qt = gridDim.x - 1 - blockIdx.x;   // heavy tiles first
    const int bh = blockIdx.y;
    const int b  = bh >> 4;
    const int h  = bh & 15;

    const __half* base = qkv + (size_t)b * T_ * C3_;
    const int qcol = h * HD_;
    const int kcol = C_ + h * HD_;
    const int vcol = 2 * C_ + h * HD_;

    // Q tile 128x64 halves -> smem (SW128), once
    {
        #pragma unroll
        for (int p = 0; p < 4; p++) {
            int idx = tid + p * 256;
            int r = idx >> 3, c = idx & 7;
            cp_async16(smc + Q_OFF + SWZ128(r * 128 + c * 16),
                       base + (size_t)(qt * 128 + r) * C3_ + qcol + c * 8);
        }
    }

    auto load_kv = [&](int j, int s) {
        #pragma unroll
        for (int p = 0; p < 2; p++) {
            int idx = tid + p * 256;
            int r = idx >> 3, c = idx & 7;
            const size_t grow = (size_t)(j * 64 + r) * C3_;
            const int so = SWZ128(r * 128 + c * 16);
            cp_async16(smc + K_OFF + s * 8192 + so, base + grow + kcol + c * 8);
            cp_async16(smc + V_OFF + s * 8192 + so, base + grow + vcol + c * 8);
        }
    };

    load_kv(0, 0); CP_COMMIT;
    CP_WAIT_0; __syncthreads();

    // Q a-frags from smem
    uint32_t qf[4][4];
    #pragma unroll
    for (int ks = 0; ks < 4; ks++) {
        const int row = warp * 16 + (lane & 15);
        const int ch  = ks * 2 + (lane >> 4);
        ldsm4(qf[ks], sbase + Q_OFF + SWZ128(row * 128 + ch * 16));
    }

    float o[8][4];
    #pragma unroll
    for (int i = 0; i < 8; i++)
        #pragma unroll
        for (int jj = 0; jj < 4; jj++) o[i][jj] = 0.f;
    float m0 = -INFINITY, m1 = -INFINITY, l0 = 0.f, l1 = 0.f;

    const float SC = 0.125f * 1.4426950408889634f;   // 1/sqrt(64) * log2(e)
    const uint32_t pwB = sbase + P_OFF + warp * 2048;
    char* pwC = smc + P_OFF + warp * 2048;

    const int jend = 2 * qt + 1;
    for (int j = 0; j <= jend; j++) {
        const int cur = j & 1;
        if (j < jend) { load_kv(j + 1, cur ^ 1); CP_COMMIT; CP_WAIT_1; }
        else          { CP_WAIT_0; }
        __syncthreads();

        const uint32_t kS = sbase + K_OFF + cur * 8192;
        const uint32_t vS = sbase + V_OFF + cur * 8192;

        // S = Q @ K^T   (K b-frags via ldmatrix non-trans on [kv][d])
        float s[8][4];
        #pragma unroll
        for (int nt = 0; nt < 8; nt++)
            #pragma unroll
            for (int k4 = 0; k4 < 4; k4++) s[nt][k4] = 0.f;

        #pragma unroll
        for (int ks = 0; ks < 4; ks++) {
            uint32_t bf[8][2];
            #pragma unroll
            for (int pr = 0; pr < 4; pr++) {
                const int row = pr * 16 + (lane & 7) + ((lane >> 4) << 3);
                const int ch  = ks * 2 + ((lane >> 3) & 1);
                uint32_t r0, r1, r2, r3;
                ldsm4(bf[pr * 2], kS + SWZ128(row * 128 + ch * 16));
                // ldsm4 wrote 4 regs into bf[pr*2][0..1] + bf[pr*2+1][0..1]? No:
                // ldsm4 takes uint32_t[4]; bf[pr*2] is [2]. Handle explicitly:
                (void)r0; (void)r1; (void)r2; (void)r3;
            }
            // The above call pattern is wrong for array shape; do it explicitly:
            #pragma unroll
            for (int pr = 0; pr < 4; pr++) {
                const int row = pr * 16 + (lane & 7) + ((lane >> 4) << 3);
                const int ch  = ks * 2 + ((lane >> 3) & 1);
                uint32_t rr[4];
                ldsm4(rr, kS + SWZ128(row * 128 + ch * 16));
                bf[pr * 2][0] = rr[0];     bf[pr * 2][1] = rr[1];
                bf[pr * 2 + 1][0] = rr[2]; bf[pr * 2 + 1][1] = rr[3];
            }
            #pragma unroll
            for (int nt = 0; nt < 8; nt++)
                mma_f16(s[nt], qf[ks], bf[nt]);
        }

        // scale (fp32, exact w.r.t. mask)
        #pragma unroll
        for (int nt = 0; nt < 8; nt++) {
            s[nt][0] *= SC; s[nt][1] *= SC; s[nt][2] *= SC; s[nt][3] *= SC;
        }

        // causal mask (diagonal-overlapping tiles only)
        if (j >= 2 * qt) {
            const int rg0 = qt * 128 + warp * 16 + g;
            const int rg1 = rg0 + 8;
            #pragma unroll
            for (int nt = 0; nt < 8; nt++) {
                const int c0 = j * 64 + nt * 8 + 2 * tg;
                if (c0     > rg0) s[nt][0] = -1e30f;
                if (c0 + 1 > rg0) s[nt][1] = -1e30f;
                if (c0     > rg1) s[nt][2] = -1e30f;
                if (c0 + 1 > rg1) s[nt][3] = -1e30f;
            }
        }

        // online softmax, base-2 (row g -> s[.][0,1]; row g+8 -> s[.][2,3])
        float mt0 = -INFINITY, mt1 = -INFINITY;
        #pragma unroll
        for (int nt = 0; nt < 8; nt++) {
            mt0 = fmaxf(mt0, fmaxf(s[nt][0], s[nt][1]));
            mt1 = fmaxf(mt1, fmaxf(s[nt][2], s[nt][3]));
        }
        mt0 = fmaxf(mt0, __shfl_xor_sync(0xffffffffu, mt0, 1));
        mt0 = fmaxf(mt0, __shfl_xor_sync(0xffffffffu, mt0, 2));
        mt1 = fmaxf(mt1, __shfl_xor_sync(0xffffffffu, mt1, 1));
        mt1 = fmaxf(mt1, __shfl_xor_sync(0xffffffffu, mt1, 2));

        const float mn0 = fmaxf(m0, mt0), mn1 = fmaxf(m1, mt1);
        const float f0 = exp2f(m0 - mn0), f1 = exp2f(m1 - mn1);

        float ls0 = 0.f, ls1 = 0.f;
        #pragma unroll
        for (int nt = 0; nt < 8; nt++) {
            const float p0 = exp2f(s[nt][0] - mn0);
            const float p1 = exp2f(s[nt][1] - mn0);
            const float p2 = exp2f(s[nt][2] - mn1);
            const float p3 = exp2f(s[nt][3] - mn1);
            ls0 += p0 + p1; ls1 += p2 + p3;
            const int c = nt * 8 + 2 * tg;   // halves
            *(__half2*)(pwC + SWZ128(g * 128 + c * 2))       = __floats2half2_rn(p0, p1);
            *(__half2*)(pwC + SWZ128((g + 8) * 128 + c * 2)) = __floats2half2_rn(p2, p3);
        }
        ls0 += __shfl_xor_sync(0xffffffffu, ls0, 1);
        ls0 += __shfl_xor_sync(0xffffffffu, ls0, 2);
        ls1 += __shfl_xor_sync(0xffffffffu, ls1, 1);
        ls1 += __shfl_xor_sync(0xffffffffu, ls1, 2);

        l0 = l0 * f0 + ls0;
        l1 = l1 * f1 + ls1;
        m0 = mn0; m1 = mn1;

        #pragma unroll
        for (int nt = 0; nt < 8; nt++) {
            o[nt][0] *= f0; o[nt][1] *= f0;
            o[nt][2] *= f1; o[nt][3] *= f1;
        }
        __syncwarp();   // per-warp P writes -> ldmatrix reads

        // O += P @ V   (P a-frags via ldmatrix, V b-frags via ldmatrix.trans)
        #pragma unroll
        for (int ks = 0; ks < 4; ks++) {
            uint32_t pf[4];
            {
                const int row = (lane & 15);
                const int ch  = ks * 2 + (lane >> 4);
                ldsm4(pf, pwB + SWZ128(row * 128 + ch * 16));
            }
            uint32_t bf[8][2];
            #pragma unroll
            for (int pr = 0; pr < 4; pr++) {
                const int row = ks * 16 + (lane & 15);
                const int ch  = pr * 2 + (lane >> 4);
                uint32_t r0, r1, r2, r3;
                ldsm4t(r0, r1, r2, r3, vS + SWZ128(row * 128 + ch * 16));
                bf[pr * 2][0] = r0;     bf[pr * 2][1] = r1;
                bf[pr * 2 + 1][0] = r2; bf[pr * 2 + 1][1] = r3;
            }
            #pragma unroll
            for (int nt = 0; nt < 8; nt++)
                mma_f16(o[nt], pf, bf[nt]);
        }
        __syncthreads();   // buf[cur] reads done before refill at j+2
    }

    // normalize + write y (half)
    const float i0 = 1.f / l0, i1 = 1.f / l1;
    const int r0 = b * T_ + qt * 128 + warp * 16 + g;
    #pragma unroll
    for (int nt = 0; nt < 8; nt++) {
        const int c = h * HD_ + nt * 8 + 2 * tg;
        *(__half2*)&y[(size_t)r0 * C_ + c] =
            __floats2half2_rn(o[nt][0] * i0, o[nt][1] * i0);
        *(__half2*)&y[(size_t)(r0 + 8) * C_ + c] =
            __floats2half2_rn(o[nt][2] * i1, o[nt][3] * i1);
    }
}

// ---------------------------------------------------------------------------
// Launch chain: convert -> qkv GEMM -> attention -> proj GEMM
// ---------------------------------------------------------------------------
extern "C" void kernel_launch(void* const* d_in, const int* in_sizes, int n_in,
                              void* d_out, int out_size)
{
    (void)in_sizes; (void)n_in; (void)out_size;
    const float* x      = (const float*)d_in[0];
    const float* w_attn = (const float*)d_in[1];
    const float* w_proj = (const float*)d_in[2];
    float* out = (float*)d_out;

    __half *qkv, *y, *xh, *wah, *wph;
    cudaGetSymbolAddress((void**)&qkv, g_qkv);
    cudaGetSymbolAddress((void**)&y,   g_y);
    cudaGetSymbolAddress((void**)&xh,  g_xh);
    cudaGetSymbolAddress((void**)&wah, g_wah);
    cudaGetSymbolAddress((void**)&wph, g_wph);

    cudaFuncSetAttribute(gemm_f16<true>,  cudaFuncAttributeMaxDynamicSharedMemorySize, GEMM_SMEM);
    cudaFuncSetAttribute(gemm_f16<false>, cudaFuncAttributeMaxDynamicSharedMemorySize, GEMM_SMEM);
    cudaFuncSetAttribute(attn_kernel,     cudaFuncAttributeMaxDynamicSharedMemorySize, ATT_SMEM);

    const int n4x = ROWS_ * C_ / 4;
    const int n4a = C_ * C3_ / 4;
    const int n4p = C_ * C_ / 4;
    to_half_kernel<<<(n4x + 255) / 256, 256>>>((const float4*)x,      (uint2*)xh,  n4x);
    to_half_kernel<<<(n4a + 255) / 256, 256>>>((const float4*)w_attn, (uint2*)wah, n4a);
    to_half_kernel<<<(n4p + 255) / 256, 256>>>((const float4*)w_proj, (uint2*)wph, n4p);

    gemm_f16<true><<<dim3(C3_ / BN, ROWS_ / BM), 256, GEMM_SMEM>>>(xh, wah, qkv, ROWS_, C3_, C_);
    attn_kernel<<<dim3(T_ / 128, B_ * NH_), 256, ATT_SMEM>>>(qkv, y);
    gemm_f16<false><<<dim3(C_ / BN, ROWS_ / BM), 256, GEMM_SMEM>>>(y, wph, out, ROWS_, C_, C_);
}

// round 8
// speedup vs baseline: 2.5138x; 1.1730x over previous
#include <cuda_runtime.h>
#include <cuda_fp16.h>
#include <cstdint>
#include <cstddef>

#define B_   2
#define T_   2048
#define C_   1024
#define NH_  16
#define HD_  64
#define C3_  3072
#define ROWS_ 4096

// ---------------------------------------------------------------------------
// Scratch (__device__ globals; allocation-free rule). All intermediates fp16.
// ---------------------------------------------------------------------------
__device__ __half g_qkv[(size_t)ROWS_ * C3_];   // 24 MB
__device__ __half g_y[(size_t)ROWS_ * C_];      //  8 MB
__device__ __half g_xh[(size_t)ROWS_ * C_];     //  8 MB  x -> half
__device__ __half g_wah[(size_t)C_ * C3_];      //  6 MB  w_attn -> half
__device__ __half g_wph[(size_t)C_ * C_];       //  2 MB  w_proj -> half

// ---------------------------------------------------------------------------
// Helpers (sm_80-era ISA only; harness ptxas target lacks the 'a' suffix)
// ---------------------------------------------------------------------------
__device__ __forceinline__ void cp_async16(void* smem_dst, const void* gsrc) {
    uint32_t s = (uint32_t)__cvta_generic_to_shared(smem_dst);
    asm volatile("cp.async.cg.shared.global [%0], [%1], 16;\n" :: "r"(s), "l"(gsrc));
}
#define CP_COMMIT asm volatile("cp.async.commit_group;\n" ::: "memory")
#define CP_WAIT_1 asm volatile("cp.async.wait_group 1;\n" ::: "memory")
#define CP_WAIT_0 asm volatile("cp.async.wait_group 0;\n" ::: "memory")

// SW128 swizzle on byte offsets within a tile of 128-byte rows
#define SWZ128(off) ((off) ^ (((off) >> 3) & 0x70))

__device__ __forceinline__ void ldsm4(uint32_t r[4], uint32_t addr) {
    asm volatile("ldmatrix.sync.aligned.m8n8.x4.shared.b16 {%0,%1,%2,%3}, [%4];"
        : "=r"(r[0]), "=r"(r[1]), "=r"(r[2]), "=r"(r[3]) : "r"(addr));
}
__device__ __forceinline__ void ldsm4t(uint32_t& r0, uint32_t& r1, uint32_t& r2, uint32_t& r3,
                                       uint32_t addr) {
    asm volatile("ldmatrix.sync.aligned.m8n8.x4.trans.shared.b16 {%0,%1,%2,%3}, [%4];"
        : "=r"(r0), "=r"(r1), "=r"(r2), "=r"(r3) : "r"(addr));
}

__device__ __forceinline__ void mma_f16(float d[4], const uint32_t a[4], const uint32_t b[2]) {
    asm volatile(
        "mma.sync.aligned.m16n8k16.row.col.f32.f16.f16.f32 "
        "{%0,%1,%2,%3}, {%4,%5,%6,%7}, {%8,%9}, {%0,%1,%2,%3};\n"
        : "+f"(d[0]), "+f"(d[1]), "+f"(d[2]), "+f"(d[3])
        : "r"(a[0]), "r"(a[1]), "r"(a[2]), "r"(a[3]), "r"(b[0]), "r"(b[1]));
}

__device__ __forceinline__ float ex2f(float x) {
    float y;
    asm("ex2.approx.ftz.f32 %0, %1;" : "=f"(y) : "f"(x));
    return y;
}

// ---------------------------------------------------------------------------
// Fused fp32 -> fp16 convert for x, w_attn, w_proj in one launch
// ---------------------------------------------------------------------------
__global__ void convert_all_kernel(const float4* __restrict__ x,  uint2* __restrict__ xh,
                                   const float4* __restrict__ wa, uint2* __restrict__ wah,
                                   const float4* __restrict__ wp, uint2* __restrict__ wph,
                                   int n4x, int n4a, int n4p)
{
    int i = blockIdx.x * 256 + threadIdx.x;
    const float4* src;
    uint2* dst;
    int j;
    if (i < n4x)            { src = x;  dst = xh;  j = i; }
    else if (i < n4x + n4a) { src = wa; dst = wah; j = i - n4x; }
    else if (i < n4x + n4a + n4p) { src = wp; dst = wph; j = i - n4x - n4a; }
    else return;
    float4 v = src[j];
    __half2 a = __floats2half2_rn(v.x, v.y);
    __half2 b = __floats2half2_rn(v.z, v.w);
    dst[j] = make_uint2(*(uint32_t*)&a, *(uint32_t*)&b);
}

// ---------------------------------------------------------------------------
// fp16 GEMM: C[M,N] = A[M,K] * B[K,N]  (A,B half; C half or float)
// Block 128x128x64, 128 threads (4 warps), warp grid 2(m)x2(n),
// warp tile 64x64 -> smem read redundancy 2xA + 2xB (was 2x + 4x).
// ldmatrix + m16n8k16, swizzled smem, 2-stage cp.async.
// ---------------------------------------------------------------------------
#define BM 128
#define BN 128
#define BK 64
#define A_ST_BYTES (BM * 128)                 // rows of 64 halves = 128 B
#define B_ST_BYTES (BK * 256)                 // rows of 128 halves = 256 B
#define STG_BYTES (A_ST_BYTES + B_ST_BYTES)   // 32768
#define GEMM_SMEM (2 * STG_BYTES)             // 65536

template<bool OUT_HALF>
__global__ __launch_bounds__(128, 2)
void gemm_f16(const __half* __restrict__ A, const __half* __restrict__ Bm,
              void* __restrict__ Cv, int M, int N, int K)
{
    extern __shared__ char smc[];
    const uint32_t sbase = (uint32_t)__cvta_generic_to_shared(smc);
    const int tid  = threadIdx.x;
    const int lane = tid & 31;
    const int warp = tid >> 5;        // 0..3
    const int wm   = warp & 1;
    const int wn   = warp >> 1;
    const int g    = lane >> 2;
    const int tg   = lane & 3;
    const int bm   = blockIdx.y * BM;
    const int bn   = blockIdx.x * BN;

    float acc[4][8][4];
    #pragma unroll
    for (int i = 0; i < 4; i++)
        #pragma unroll
        for (int j = 0; j < 8; j++)
            #pragma unroll
            for (int k = 0; k < 4; k++) acc[i][j][k] = 0.f;

    auto load_stage = [&](int kt, int s) {
        char* As = smc + s * STG_BYTES;
        char* Bs = As + A_ST_BYTES;
        #pragma unroll
        for (int p = 0; p < 8; p++) {        // A: 128 rows x 8 chunks of 16B
            int idx = tid + p * 128;
            int r = idx >> 3, c = idx & 7;
            cp_async16(As + SWZ128(r * 128 + c * 16),
                       A + (size_t)(bm + r) * K + kt * BK + c * 8);
        }
        #pragma unroll
        for (int p = 0; p < 8; p++) {        // B: 64 rows x 16 chunks (256B rows)
            int idx = tid + p * 128;
            int r = idx >> 4, c = idx & 15;
            cp_async16(Bs + r * 256 + ((c ^ (r & 7)) * 16),
                       Bm + (size_t)(kt * BK + r) * N + bn + c * 8);
        }
    };

    const int nk = K / BK;
    load_stage(0, 0); CP_COMMIT;

    for (int kt = 0; kt < nk; kt++) {
        const int cur = kt & 1;
        if (kt + 1 < nk) { load_stage(kt + 1, cur ^ 1); CP_COMMIT; CP_WAIT_1; }
        else             { CP_WAIT_0; }
        __syncthreads();

        const uint32_t aS = sbase + cur * STG_BYTES;
        const uint32_t bS = aS + A_ST_BYTES;

        #pragma unroll
        for (int ks = 0; ks < 4; ks++) {
            uint32_t af[4][4];
            #pragma unroll
            for (int mt = 0; mt < 4; mt++) {
                const int row = wm * 64 + mt * 16 + (lane & 15);
                const int ch  = ks * 2 + (lane >> 4);
                ldsm4(af[mt], aS + SWZ128(row * 128 + ch * 16));
            }
            uint32_t bf[8][2];
            #pragma unroll
            for (int pr = 0; pr < 4; pr++) {
                const int row = ks * 16 + (lane & 7) + (lane & 8);
                const int ch  = wn * 8 + pr * 2 + (lane >> 4);
                uint32_t r0, r1, r2, r3;
                ldsm4t(r0, r1, r2, r3, bS + row * 256 + ((ch ^ (row & 7)) * 16));
                bf[pr * 2][0] = r0;     bf[pr * 2][1] = r1;
                bf[pr * 2 + 1][0] = r2; bf[pr * 2 + 1][1] = r3;
            }
            #pragma unroll
            for (int mt = 0; mt < 4; mt++)
                #pragma unroll
                for (int nt = 0; nt < 8; nt++)
                    mma_f16(acc[mt][nt], af[mt], bf[nt]);
        }
        __syncthreads();
    }

    // Epilogue: c0,c1 -> (row g, cols 2tg,2tg+1); c2,c3 -> row g+8
    #pragma unroll
    for (int mt = 0; mt < 4; mt++) {
        const int r0 = bm + wm * 64 + mt * 16 + g;
        #pragma unroll
        for (int nt = 0; nt < 8; nt++) {
            const int cc = bn + wn * 64 + nt * 8 + 2 * tg;
            if (OUT_HALF) {
                __half* Ch = (__half*)Cv;
                *(__half2*)&Ch[(size_t)r0 * N + cc]       = __floats2half2_rn(acc[mt][nt][0], acc[mt][nt][1]);
                *(__half2*)&Ch[(size_t)(r0 + 8) * N + cc] = __floats2half2_rn(acc[mt][nt][2], acc[mt][nt][3]);
            } else {
                float* Cf = (float*)Cv;
                *(float2*)&Cf[(size_t)r0 * N + cc]       = make_float2(acc[mt][nt][0], acc[mt][nt][1]);
                *(float2*)&Cf[(size_t)(r0 + 8) * N + cc] = make_float2(acc[mt][nt][2], acc[mt][nt][3]);
            }
        }
    }
}

// ---------------------------------------------------------------------------
// Flash attention, fp16 MMA. One block per (q-tile of 128, b*h).
// 8 warps x 16 q-rows; KV tile 64; HD=64. Softmax fp32, base-2.
// smem (bytes): Q[0,16K) K[16K,32K) x2  V[32K,48K) x2  P[48K,64K)
// ---------------------------------------------------------------------------
#define Q_OFF 0
#define K_OFF 16384
#define V_OFF 32768
#define P_OFF 49152
#define ATT_SMEM 65536

__global__ __launch_bounds__(256, 2)
void attn_kernel(const __half* __restrict__ qkv, __half* __restrict__ y)
{
    extern __shared__ char smc[];
    const uint32_t sbase = (uint32_t)__cvta_generic_to_shared(smc);
    const int tid  = threadIdx.x;
    const int lane = tid & 31;
    const int warp = tid >> 5;
    const int g    = lane >> 2;
    const int tg   = lane & 3;

    const int qt = gridDim.x - 1 - blockIdx.x;   // heavy tiles first
    const int bh = blockIdx.y;
    const int b  = bh >> 4;
    const int h  = bh & 15;

    const __half* base = qkv + (size_t)b * T_ * C3_;
    const int qcol = h * HD_;
    const int kcol = C_ + h * HD_;
    const int vcol = 2 * C_ + h * HD_;

    // Q tile 128x64 halves -> smem (SW128), once
    #pragma unroll
    for (int p = 0; p < 4; p++) {
        int idx = tid + p * 256;
        int r = idx >> 3, c = idx & 7;
        cp_async16(smc + Q_OFF + SWZ128(r * 128 + c * 16),
                   base + (size_t)(qt * 128 + r) * C3_ + qcol + c * 8);
    }

    auto load_kv = [&](int j, int s) {
        #pragma unroll
        for (int p = 0; p < 2; p++) {
            int idx = tid + p * 256;
            int r = idx >> 3, c = idx & 7;
            const size_t grow = (size_t)(j * 64 + r) * C3_;
            const int so = SWZ128(r * 128 + c * 16);
            cp_async16(smc + K_OFF + s * 8192 + so, base + grow + kcol + c * 8);
            cp_async16(smc + V_OFF + s * 8192 + so, base + grow + vcol + c * 8);
        }
    };

    load_kv(0, 0); CP_COMMIT;
    CP_WAIT_0; __syncthreads();

    // Q a-frags from smem (held in registers for the whole kv loop)
    uint32_t qf[4][4];
    #pragma unroll
    for (int ks = 0; ks < 4; ks++) {
        const int row = warp * 16 + (lane & 15);
        const int ch  = ks * 2 + (lane >> 4);
        ldsm4(qf[ks], sbase + Q_OFF + SWZ128(row * 128 + ch * 16));
    }

    float o[8][4];
    #pragma unroll
    for (int i = 0; i < 8; i++)
        #pragma unroll
        for (int jj = 0; jj < 4; jj++) o[i][jj] = 0.f;
    float m0 = -INFINITY, m1 = -INFINITY, l0 = 0.f, l1 = 0.f;

    const float SC = 0.125f * 1.4426950408889634f;   // 1/sqrt(64) * log2(e)
    const uint32_t pwB = sbase + P_OFF + warp * 2048;
    char* pwC = smc + P_OFF + warp * 2048;

    const int jend = 2 * qt + 1;
    for (int j = 0; j <= jend; j++) {
        const int cur = j & 1;
        if (j < jend) { load_kv(j + 1, cur ^ 1); CP_COMMIT; CP_WAIT_1; }
        else          { CP_WAIT_0; }
        __syncthreads();

        const uint32_t kS = sbase + K_OFF + cur * 8192;
        const uint32_t vS = sbase + V_OFF + cur * 8192;

        // S = Q @ K^T   (K b-frags via ldmatrix non-trans on [kv][d])
        float s[8][4];
        #pragma unroll
        for (int nt = 0; nt < 8; nt++)
            #pragma unroll
            for (int k4 = 0; k4 < 4; k4++) s[nt][k4] = 0.f;

        #pragma unroll
        for (int ks = 0; ks < 4; ks++) {
            uint32_t bf[8][2];
            #pragma unroll
            for (int pr = 0; pr < 4; pr++) {
                const int row = pr * 16 + (lane & 7) + ((lane >> 4) << 3);
                const int ch  = ks * 2 + ((lane >> 3) & 1);
                uint32_t rr[4];
                ldsm4(rr, kS + SWZ128(row * 128 + ch * 16));
                bf[pr * 2][0] = rr[0];     bf[pr * 2][1] = rr[1];
                bf[pr * 2 + 1][0] = rr[2]; bf[pr * 2 + 1][1] = rr[3];
            }
            #pragma unroll
            for (int nt = 0; nt < 8; nt++)
                mma_f16(s[nt], qf[ks], bf[nt]);
        }

        // scale (fp32)
        #pragma unroll
        for (int nt = 0; nt < 8; nt++) {
            s[nt][0] *= SC; s[nt][1] *= SC; s[nt][2] *= SC; s[nt][3] *= SC;
        }

        // causal mask (diagonal-overlapping tiles only)
        if (j >= 2 * qt) {
            const int rg0 = qt * 128 + warp * 16 + g;
            const int rg1 = rg0 + 8;
            #pragma unroll
            for (int nt = 0; nt < 8; nt++) {
                const int c0 = j * 64 + nt * 8 + 2 * tg;
                if (c0     > rg0) s[nt][0] = -1e30f;
                if (c0 + 1 > rg0) s[nt][1] = -1e30f;
                if (c0     > rg1) s[nt][2] = -1e30f;
                if (c0 + 1 > rg1) s[nt][3] = -1e30f;
            }
        }

        // online softmax, base-2 (row g -> s[.][0,1]; row g+8 -> s[.][2,3])
        float mt0 = -INFINITY, mt1 = -INFINITY;
        #pragma unroll
        for (int nt = 0; nt < 8; nt++) {
            mt0 = fmaxf(mt0, fmaxf(s[nt][0], s[nt][1]));
            mt1 = fmaxf(mt1, fmaxf(s[nt][2], s[nt][3]));
        }
        mt0 = fmaxf(mt0, __shfl_xor_sync(0xffffffffu, mt0, 1));
        mt0 = fmaxf(mt0, __shfl_xor_sync(0xffffffffu, mt0, 2));
        mt1 = fmaxf(mt1, __shfl_xor_sync(0xffffffffu, mt1, 1));
        mt1 = fmaxf(mt1, __shfl_xor_sync(0xffffffffu, mt1, 2));

        const float mn0 = fmaxf(m0, mt0), mn1 = fmaxf(m1, mt1);
        const float f0 = ex2f(m0 - mn0), f1 = ex2f(m1 - mn1);

        float ls0 = 0.f, ls1 = 0.f;
        #pragma unroll
        for (int nt = 0; nt < 8; nt++) {
            const float p0 = ex2f(s[nt][0] - mn0);
            const float p1 = ex2f(s[nt][1] - mn0);
            const float p2 = ex2f(s[nt][2] - mn1);
            const float p3 = ex2f(s[nt][3] - mn1);
            ls0 += p0 + p1; ls1 += p2 + p3;
            const int c = nt * 8 + 2 * tg;   // halves
            *(__half2*)(pwC + SWZ128(g * 128 + c * 2))       = __floats2half2_rn(p0, p1);
            *(__half2*)(pwC + SWZ128((g + 8) * 128 + c * 2)) = __floats2half2_rn(p2, p3);
        }
        ls0 += __shfl_xor_sync(0xffffffffu, ls0, 1);
        ls0 += __shfl_xor_sync(0xffffffffu, ls0, 2);
        ls1 += __shfl_xor_sync(0xffffffffu, ls1, 1);
        ls1 += __shfl_xor_sync(0xffffffffu, ls1, 2);

        l0 = l0 * f0 + ls0;
        l1 = l1 * f1 + ls1;
        m0 = mn0; m1 = mn1;

        #pragma unroll
        for (int nt = 0; nt < 8; nt++) {
            o[nt][0] *= f0; o[nt][1] *= f0;
            o[nt][2] *= f1; o[nt][3] *= f1;
        }
        __syncwarp();   // per-warp P writes -> ldmatrix reads

        // O += P @ V   (P a-frags via ldmatrix, V b-frags via ldmatrix.trans)
        #pragma unroll
        for (int ks = 0; ks < 4; ks++) {
            uint32_t pf[4];
            {
                const int row = (lane & 15);
                const int ch  = ks * 2 + (lane >> 4);
                ldsm4(pf, pwB + SWZ128(row * 128 + ch * 16));
            }
            uint32_t bf[8][2];
            #pragma unroll
            for (int pr = 0; pr < 4; pr++) {
                const int row = ks * 16 + (lane & 15);
                const int ch  = pr * 2 + (lane >> 4);
                uint32_t r0, r1, r2, r3;
                ldsm4t(r0, r1, r2, r3, vS + SWZ128(row * 128 + ch * 16));
                bf[pr * 2][0] = r0;     bf[pr * 2][1] = r1;
                bf[pr * 2 + 1][0] = r2; bf[pr * 2 + 1][1] = r3;
            }
            #pragma unroll
            for (int nt = 0; nt < 8; nt++)
                mma_f16(o[nt], pf, bf[nt]);
        }
        __syncthreads();   // buf[cur] reads done before refill at j+2
    }

    // normalize + write y (half)
    const float i0 = 1.f / l0, i1 = 1.f / l1;
    const int r0 = b * T_ + qt * 128 + warp * 16 + g;
    #pragma unroll
    for (int nt = 0; nt < 8; nt++) {
        const int c = h * HD_ + nt * 8 + 2 * tg;
        *(__half2*)&y[(size_t)r0 * C_ + c] =
            __floats2half2_rn(o[nt][0] * i0, o[nt][1] * i0);
        *(__half2*)&y[(size_t)(r0 + 8) * C_ + c] =
            __floats2half2_rn(o[nt][2] * i1, o[nt][3] * i1);
    }
}

// ---------------------------------------------------------------------------
// Launch chain: convert -> qkv GEMM -> attention -> proj GEMM
// ---------------------------------------------------------------------------
extern "C" void kernel_launch(void* const* d_in, const int* in_sizes, int n_in,
                              void* d_out, int out_size)
{
    (void)in_sizes; (void)n_in; (void)out_size;
    const float* x      = (const float*)d_in[0];
    const float* w_attn = (const float*)d_in[1];
    const float* w_proj = (const float*)d_in[2];
    float* out = (float*)d_out;

    __half *qkv, *y, *xh, *wah, *wph;
    cudaGetSymbolAddress((void**)&qkv, g_qkv);
    cudaGetSymbolAddress((void**)&y,   g_y);
    cudaGetSymbolAddress((void**)&xh,  g_xh);
    cudaGetSymbolAddress((void**)&wah, g_wah);
    cudaGetSymbolAddress((void**)&wph, g_wph);

    cudaFuncSetAttribute(gemm_f16<true>,  cudaFuncAttributeMaxDynamicSharedMemorySize, GEMM_SMEM);
    cudaFuncSetAttribute(gemm_f16<false>, cudaFuncAttributeMaxDynamicSharedMemorySize, GEMM_SMEM);
    cudaFuncSetAttribute(attn_kernel,     cudaFuncAttributeMaxDynamicSharedMemorySize, ATT_SMEM);

    const int n4x = ROWS_ * C_ / 4;       // 1048576
    const int n4a = C_ * C3_ / 4;         // 786432
    const int n4p = C_ * C_ / 4;          // 262144
    const int n4  = n4x + n4a + n4p;
    convert_all_kernel<<<(n4 + 255) / 256, 256>>>(
        (const float4*)x, (uint2*)xh,
        (const float4*)w_attn, (uint2*)wah,
        (const float4*)w_proj, (uint2*)wph,
        n4x, n4a, n4p);

    gemm_f16<true><<<dim3(C3_ / BN, ROWS_ / BM), 128, GEMM_SMEM>>>(xh, wah, qkv, ROWS_, C3_, C_);
    attn_kernel<<<dim3(T_ / 128, B_ * NH_), 256, ATT_SMEM>>>(qkv, y);
    gemm_f16<false><<<dim3(C_ / BN, ROWS_ / BM), 128, GEMM_SMEM>>>(y, wph, out, ROWS_, C_, C_);
}

// round 9
// speedup vs baseline: 2.5882x; 1.0296x over previous
#include <cuda_runtime.h>
#include <cuda_fp16.h>
#include <cstdint>
#include <cstddef>

#define B_   2
#define T_   2048
#define C_   1024
#define NH_  16
#define HD_  64
#define C3_  3072
#define ROWS_ 4096

// ---------------------------------------------------------------------------
// Scratch (__device__ globals; allocation-free rule). All intermediates fp16.
// ---------------------------------------------------------------------------
__device__ __half g_qkv[(size_t)ROWS_ * C3_];   // 24 MB
__device__ __half g_y[(size_t)ROWS_ * C_];      //  8 MB
__device__ __half g_xh[(size_t)ROWS_ * C_];     //  8 MB  x -> half
__device__ __half g_wah[(size_t)C_ * C3_];      //  6 MB  w_attn -> half
__device__ __half g_wph[(size_t)C_ * C_];       //  2 MB  w_proj -> half

// ---------------------------------------------------------------------------
// Helpers (sm_80-era ISA only; harness ptxas target lacks the 'a' suffix)
// ---------------------------------------------------------------------------
__device__ __forceinline__ void cp_async16(void* smem_dst, const void* gsrc) {
    uint32_t s = (uint32_t)__cvta_generic_to_shared(smem_dst);
    asm volatile("cp.async.cg.shared.global [%0], [%1], 16;\n" :: "r"(s), "l"(gsrc));
}
#define CP_COMMIT asm volatile("cp.async.commit_group;\n" ::: "memory")
#define CP_WAIT_0 asm volatile("cp.async.wait_group 0;\n" ::: "memory")

// SW128 swizzle on byte offsets within a tile of 128-byte rows
#define SWZ128(off) ((off) ^ (((off) >> 3) & 0x70))

__device__ __forceinline__ void ldsm4(uint32_t r[4], uint32_t addr) {
    asm volatile("ldmatrix.sync.aligned.m8n8.x4.shared.b16 {%0,%1,%2,%3}, [%4];"
        : "=r"(r[0]), "=r"(r[1]), "=r"(r[2]), "=r"(r[3]) : "r"(addr));
}
__device__ __forceinline__ void ldsm4t(uint32_t& r0, uint32_t& r1, uint32_t& r2, uint32_t& r3,
                                       uint32_t addr) {
    asm volatile("ldmatrix.sync.aligned.m8n8.x4.trans.shared.b16 {%0,%1,%2,%3}, [%4];"
        : "=r"(r0), "=r"(r1), "=r"(r2), "=r"(r3) : "r"(addr));
}

__device__ __forceinline__ void mma_f16(float d[4], const uint32_t a[4], const uint32_t b[2]) {
    asm volatile(
        "mma.sync.aligned.m16n8k16.row.col.f32.f16.f16.f32 "
        "{%0,%1,%2,%3}, {%4,%5,%6,%7}, {%8,%9}, {%0,%1,%2,%3};\n"
        : "+f"(d[0]), "+f"(d[1]), "+f"(d[2]), "+f"(d[3])
        : "r"(a[0]), "r"(a[1]), "r"(a[2]), "r"(a[3]), "r"(b[0]), "r"(b[1]));
}

__device__ __forceinline__ float ex2f(float x) {
    float y;
    asm("ex2.approx.ftz.f32 %0, %1;" : "=f"(y) : "f"(x));
    return y;
}

// pack two floats to f16x2: lo -> low half, hi -> high half
__device__ __forceinline__ uint32_t pack_h2(float lo, float hi) {
    uint32_t u;
    asm("cvt.rn.f16x2.f32 %0, %1, %2;" : "=r"(u) : "f"(hi), "f"(lo));
    return u;
}

// ---------------------------------------------------------------------------
// Fused fp32 -> fp16 convert for x, w_attn, w_proj in one launch
// ---------------------------------------------------------------------------
__global__ void convert_all_kernel(const float4* __restrict__ x,  uint2* __restrict__ xh,
                                   const float4* __restrict__ wa, uint2* __restrict__ wah,
                                   const float4* __restrict__ wp, uint2* __restrict__ wph,
                                   int n4x, int n4a, int n4p)
{
    int i = blockIdx.x * 256 + threadIdx.x;
    const float4* src;
    uint2* dst;
    int j;
    if (i < n4x)            { src = x;  dst = xh;  j = i; }
    else if (i < n4x + n4a) { src = wa; dst = wah; j = i - n4x; }
    else if (i < n4x + n4a + n4p) { src = wp; dst = wph; j = i - n4x - n4a; }
    else return;
    float4 v = src[j];
    __half2 a = __floats2half2_rn(v.x, v.y);
    __half2 b = __floats2half2_rn(v.z, v.w);
    dst[j] = make_uint2(*(uint32_t*)&a, *(uint32_t*)&b);
}

// ---------------------------------------------------------------------------
// fp16 GEMM: C[M,N] = A[M,K] * B[K,N]  (A,B half; C half or float)
// Block 128x128x64, 128 threads, warp grid 2x2, warp tile 64x64.
// ldmatrix + m16n8k16, swizzled smem, 2-stage cp.async, ONE sync per k-iter.
// ---------------------------------------------------------------------------
#define BM 128
#define BN 128
#define BK 64
#define A_ST_BYTES (BM * 128)                 // rows of 64 halves = 128 B
#define B_ST_BYTES (BK * 256)                 // rows of 128 halves = 256 B
#define STG_BYTES (A_ST_BYTES + B_ST_BYTES)   // 32768
#define GEMM_SMEM (2 * STG_BYTES)             // 65536

template<bool OUT_HALF>
__global__ __launch_bounds__(128, 2)
void gemm_f16(const __half* __restrict__ A, const __half* __restrict__ Bm,
              void* __restrict__ Cv, int M, int N, int K)
{
    extern __shared__ char smc[];
    const uint32_t sbase = (uint32_t)__cvta_generic_to_shared(smc);
    const int tid  = threadIdx.x;
    const int lane = tid & 31;
    const int warp = tid >> 5;        // 0..3
    const int wm   = warp & 1;
    const int wn   = warp >> 1;
    const int g    = lane >> 2;
    const int tg   = lane & 3;
    const int bm   = blockIdx.y * BM;
    const int bn   = blockIdx.x * BN;

    float acc[4][8][4];
    #pragma unroll
    for (int i = 0; i < 4; i++)
        #pragma unroll
        for (int j = 0; j < 8; j++)
            #pragma unroll
            for (int k = 0; k < 4; k++) acc[i][j][k] = 0.f;

    auto load_stage = [&](int kt, int s) {
        char* As = smc + s * STG_BYTES;
        char* Bs = As + A_ST_BYTES;
        #pragma unroll
        for (int p = 0; p < 8; p++) {        // A: 128 rows x 8 chunks of 16B
            int idx = tid + p * 128;
            int r = idx >> 3, c = idx & 7;
            cp_async16(As + SWZ128(r * 128 + c * 16),
                       A + (size_t)(bm + r) * K + kt * BK + c * 8);
        }
        #pragma unroll
        for (int p = 0; p < 8; p++) {        // B: 64 rows x 16 chunks (256B rows)
            int idx = tid + p * 128;
            int r = idx >> 4, c = idx & 15;
            cp_async16(Bs + r * 256 + ((c ^ (r & 7)) * 16),
                       Bm + (size_t)(kt * BK + r) * N + bn + c * 8);
        }
    };

    const int nk = K / BK;
    load_stage(0, 0); CP_COMMIT;
    CP_WAIT_0; __syncthreads();

    for (int kt = 0; kt < nk; kt++) {
        const int cur = kt & 1;
        if (kt + 1 < nk) { load_stage(kt + 1, cur ^ 1); CP_COMMIT; }

        const uint32_t aS = sbase + cur * STG_BYTES;
        const uint32_t bS = aS + A_ST_BYTES;

        #pragma unroll
        for (int ks = 0; ks < 4; ks++) {
            uint32_t af[4][4];
            #pragma unroll
            for (int mt = 0; mt < 4; mt++) {
                const int row = wm * 64 + mt * 16 + (lane & 15);
                const int ch  = ks * 2 + (lane >> 4);
                ldsm4(af[mt], aS + SWZ128(row * 128 + ch * 16));
            }
            uint32_t bf[8][2];
            #pragma unroll
            for (int pr = 0; pr < 4; pr++) {
                const int row = ks * 16 + (lane & 7) + (lane & 8);
                const int ch  = wn * 8 + pr * 2 + (lane >> 4);
                uint32_t r0, r1, r2, r3;
                ldsm4t(r0, r1, r2, r3, bS + row * 256 + ((ch ^ (row & 7)) * 16));
                bf[pr * 2][0] = r0;     bf[pr * 2][1] = r1;
                bf[pr * 2 + 1][0] = r2; bf[pr * 2 + 1][1] = r3;
            }
            #pragma unroll
            for (int mt = 0; mt < 4; mt++)
                #pragma unroll
                for (int nt = 0; nt < 8; nt++)
                    mma_f16(acc[mt][nt], af[mt], bf[nt]);
        }

        if (kt + 1 < nk) { CP_WAIT_0; __syncthreads(); }
    }

    // Epilogue: c0,c1 -> (row g, cols 2tg,2tg+1); c2,c3 -> row g+8
    #pragma unroll
    for (int mt = 0; mt < 4; mt++) {
        const int r0 = bm + wm * 64 + mt * 16 + g;
        #pragma unroll
        for (int nt = 0; nt < 8; nt++) {
            const int cc = bn + wn * 64 + nt * 8 + 2 * tg;
            if (OUT_HALF) {
                __half* Ch = (__half*)Cv;
                *(__half2*)&Ch[(size_t)r0 * N + cc]       = __floats2half2_rn(acc[mt][nt][0], acc[mt][nt][1]);
                *(__half2*)&Ch[(size_t)(r0 + 8) * N + cc] = __floats2half2_rn(acc[mt][nt][2], acc[mt][nt][3]);
            } else {
                float* Cf = (float*)Cv;
                *(float2*)&Cf[(size_t)r0 * N + cc]       = make_float2(acc[mt][nt][0], acc[mt][nt][1]);
                *(float2*)&Cf[(size_t)(r0 + 8) * N + cc] = make_float2(acc[mt][nt][2], acc[mt][nt][3]);
            }
        }
    }
}

// ---------------------------------------------------------------------------
// Flash attention, fp16 MMA, P kept entirely in registers (S c-frag == P a-frag
// layout for m16n8k16). One block per (q-tile of 128, b*h); 8 warps x 16 q-rows;
// KV tile 64; softmax fp32 base-2; one __syncthreads per kv-tile.
// smem: Q[0,16K) K[16K,32K) x2(8K) V[32K,48K) x2(8K)
// ---------------------------------------------------------------------------
#define Q_OFF 0
#define K_OFF 16384
#define V_OFF 32768
#define ATT_SMEM 49152

__global__ __launch_bounds__(256, 2)
void attn_kernel(const __half* __restrict__ qkv, __half* __restrict__ y)
{
    extern __shared__ char smc[];
    const uint32_t sbase = (uint32_t)__cvta_generic_to_shared(smc);
    const int tid  = threadIdx.x;
    const int lane = tid & 31;
    const int warp = tid >> 5;
    const int g    = lane >> 2;
    const int tg   = lane & 3;

    const int qt = gridDim.x - 1 - blockIdx.x;   // heavy tiles first
    const int bh = blockIdx.y;
    const int b  = bh >> 4;
    const int h  = bh & 15;

    const __half* base = qkv + (size_t)b * T_ * C3_;
    const int qcol = h * HD_;
    const int kcol = C_ + h * HD_;
    const int vcol = 2 * C_ + h * HD_;

    // Q tile 128x64 halves -> smem (swizzled), once
    #pragma unroll
    for (int p = 0; p < 4; p++) {
        int idx = tid + p * 256;
        int r = idx >> 3, c = idx & 7;
        cp_async16(smc + Q_OFF + SWZ128(r * 128 + c * 16),
                   base + (size_t)(qt * 128 + r) * C3_ + qcol + c * 8);
    }

    auto load_kv = [&](int j, int s) {
        #pragma unroll
        for (int p = 0; p < 2; p++) {
            int idx = tid + p * 256;
            int r = idx >> 3, c = idx & 7;
            const size_t grow = (size_t)(j * 64 + r) * C3_;
            const int so = SWZ128(r * 128 + c * 16);
            cp_async16(smc + K_OFF + s * 8192 + so, base + grow + kcol + c * 8);
            cp_async16(smc + V_OFF + s * 8192 + so, base + grow + vcol + c * 8);
        }
    };

    load_kv(0, 0); CP_COMMIT;
    CP_WAIT_0; __syncthreads();

    // Q a-frags, held in registers for the whole kv loop
    uint32_t qf[4][4];
    #pragma unroll
    for (int ks = 0; ks < 4; ks++) {
        const int row = warp * 16 + (lane & 15);
        const int ch  = ks * 2 + (lane >> 4);
        ldsm4(qf[ks], sbase + Q_OFF + SWZ128(row * 128 + ch * 16));
    }

    float o[8][4];
    #pragma unroll
    for (int i = 0; i < 8; i++)
        #pragma unroll
        for (int jj = 0; jj < 4; jj++) o[i][jj] = 0.f;
    float m0 = -INFINITY, m1 = -INFINITY, l0 = 0.f, l1 = 0.f;

    const float SC = 0.125f * 1.4426950408889634f;   // 1/sqrt(64) * log2(e)

    const int jend = 2 * qt + 1;
    for (int j = 0; j <= jend; j++) {
        const int cur = j & 1;
        if (j < jend) { load_kv(j + 1, cur ^ 1); CP_COMMIT; }

        const uint32_t kS = sbase + K_OFF + cur * 8192;
        const uint32_t vS = sbase + V_OFF + cur * 8192;

        // S = Q @ K^T
        float s[8][4];
        #pragma unroll
        for (int nt = 0; nt < 8; nt++)
            #pragma unroll
            for (int k4 = 0; k4 < 4; k4++) s[nt][k4] = 0.f;

        #pragma unroll
        for (int ks = 0; ks < 4; ks++) {
            uint32_t bf[8][2];
            #pragma unroll
            for (int pr = 0; pr < 4; pr++) {
                const int row = pr * 16 + (lane & 7) + ((lane >> 4) << 3);
                const int ch  = ks * 2 + ((lane >> 3) & 1);
                uint32_t rr[4];
                ldsm4(rr, kS + SWZ128(row * 128 + ch * 16));
                bf[pr * 2][0] = rr[0];     bf[pr * 2][1] = rr[1];
                bf[pr * 2 + 1][0] = rr[2]; bf[pr * 2 + 1][1] = rr[3];
            }
            #pragma unroll
            for (int nt = 0; nt < 8; nt++)
                mma_f16(s[nt], qf[ks], bf[nt]);
        }

        // scale
        #pragma unroll
        for (int nt = 0; nt < 8; nt++) {
            s[nt][0] *= SC; s[nt][1] *= SC; s[nt][2] *= SC; s[nt][3] *= SC;
        }

        // causal mask (diagonal-overlapping tiles only)
        if (j >= 2 * qt) {
            const int rg0 = qt * 128 + warp * 16 + g;
            const int rg1 = rg0 + 8;
            #pragma unroll
            for (int nt = 0; nt < 8; nt++) {
                const int c0 = j * 64 + nt * 8 + 2 * tg;
                if (c0     > rg0) s[nt][0] = -1e30f;
                if (c0 + 1 > rg0) s[nt][1] = -1e30f;
                if (c0     > rg1) s[nt][2] = -1e30f;
                if (c0 + 1 > rg1) s[nt][3] = -1e30f;
            }
        }

        // online softmax, base-2 (row g -> s[.][0,1]; row g+8 -> s[.][2,3])
        float mt0 = -INFINITY, mt1 = -INFINITY;
        #pragma unroll
        for (int nt = 0; nt < 8; nt++) {
            mt0 = fmaxf(mt0, fmaxf(s[nt][0], s[nt][1]));
            mt1 = fmaxf(mt1, fmaxf(s[nt][2], s[nt][3]));
        }
        mt0 = fmaxf(mt0, __shfl_xor_sync(0xffffffffu, mt0, 1));
        mt0 = fmaxf(mt0, __shfl_xor_sync(0xffffffffu, mt0, 2));
        mt1 = fmaxf(mt1, __shfl_xor_sync(0xffffffffu, mt1, 1));
        mt1 = fmaxf(mt1, __shfl_xor_sync(0xffffffffu, mt1, 2));

        const float mn0 = fmaxf(m0, mt0), mn1 = fmaxf(m1, mt1);
        const float f0 = ex2f(m0 - mn0), f1 = ex2f(m1 - mn1);

        // exp + pack P directly into a-frags (c-frag layout == a-frag layout)
        uint32_t pf[4][4];
        float ls0 = 0.f, ls1 = 0.f;
        #pragma unroll
        for (int ks = 0; ks < 4; ks++) {
            const float pa0 = ex2f(s[2*ks][0] - mn0);
            const float pa1 = ex2f(s[2*ks][1] - mn0);
            const float pa2 = ex2f(s[2*ks][2] - mn1);
            const float pa3 = ex2f(s[2*ks][3] - mn1);
            const float pb0 = ex2f(s[2*ks+1][0] - mn0);
            const float pb1 = ex2f(s[2*ks+1][1] - mn0);
            const float pb2 = ex2f(s[2*ks+1][2] - mn1);
            const float pb3 = ex2f(s[2*ks+1][3] - mn1);
            ls0 += pa0 + pa1 + pb0 + pb1;
            ls1 += pa2 + pa3 + pb2 + pb3;
            pf[ks][0] = pack_h2(pa0, pa1);
            pf[ks][1] = pack_h2(pa2, pa3);
            pf[ks][2] = pack_h2(pb0, pb1);
            pf[ks][3] = pack_h2(pb2, pb3);
        }
        ls0 += __shfl_xor_sync(0xffffffffu, ls0, 1);
        ls0 += __shfl_xor_sync(0xffffffffu, ls0, 2);
        ls1 += __shfl_xor_sync(0xffffffffu, ls1, 1);
        ls1 += __shfl_xor_sync(0xffffffffu, ls1, 2);

        l0 = l0 * f0 + ls0;
        l1 = l1 * f1 + ls1;
        m0 = mn0; m1 = mn1;

        #pragma unroll
        for (int nt = 0; nt < 8; nt++) {
            o[nt][0] *= f0; o[nt][1] *= f0;
            o[nt][2] *= f1; o[nt][3] *= f1;
        }

        // O += P @ V   (P a-frags in registers; V b-frags via ldmatrix.trans)
        #pragma unroll
        for (int ks = 0; ks < 4; ks++) {
            uint32_t bf[8][2];
            #pragma unroll
            for (int pr = 0; pr < 4; pr++) {
                const int row = ks * 16 + (lane & 15);
                const int ch  = pr * 2 + (lane >> 4);
                uint32_t r0, r1, r2, r3;
                ldsm4t(r0, r1, r2, r3, vS + SWZ128(row * 128 + ch * 16));
                bf[pr * 2][0] = r0;     bf[pr * 2][1] = r1;
                bf[pr * 2 + 1][0] = r2; bf[pr * 2 + 1][1] = r3;
            }
            #pragma unroll
            for (int nt = 0; nt < 8; nt++)
                mma_f16(o[nt], pf[ks], bf[nt]);
        }

        if (j < jend) { CP_WAIT_0; __syncthreads(); }
    }

    // normalize + write y (half)
    const float i0 = 1.f / l0, i1 = 1.f / l1;
    const int r0 = b * T_ + qt * 128 + warp * 16 + g;
    #pragma unroll
    for (int nt = 0; nt < 8; nt++) {
        const int c = h * HD_ + nt * 8 + 2 * tg;
        *(__half2*)&y[(size_t)r0 * C_ + c] =
            __floats2half2_rn(o[nt][0] * i0, o[nt][1] * i0);
        *(__half2*)&y[(size_t)(r0 + 8) * C_ + c] =
            __floats2half2_rn(o[nt][2] * i1, o[nt][3] * i1);
    }
}

// ---------------------------------------------------------------------------
// Launch chain: convert -> qkv GEMM -> attention -> proj GEMM
// ---------------------------------------------------------------------------
extern "C" void kernel_launch(void* const* d_in, const int* in_sizes, int n_in,
                              void* d_out, int out_size)
{
    (void)in_sizes; (void)n_in; (void)out_size;
    const float* x      = (const float*)d_in[0];
    const float* w_attn = (const float*)d_in[1];
    const float* w_proj = (const float*)d_in[2];
    float* out = (float*)d_out;

    __half *qkv, *y, *xh, *wah, *wph;
    cudaGetSymbolAddress((void**)&qkv, g_qkv);
    cudaGetSymbolAddress((void**)&y,   g_y);
    cudaGetSymbolAddress((void**)&xh,  g_xh);
    cudaGetSymbolAddress((void**)&wah, g_wah);
    cudaGetSymbolAddress((void**)&wph, g_wph);

    cudaFuncSetAttribute(gemm_f16<true>,  cudaFuncAttributeMaxDynamicSharedMemorySize, GEMM_SMEM);
    cudaFuncSetAttribute(gemm_f16<false>, cudaFuncAttributeMaxDynamicSharedMemorySize, GEMM_SMEM);
    cudaFuncSetAttribute(attn_kernel,     cudaFuncAttributeMaxDynamicSharedMemorySize, ATT_SMEM);

    const int n4x = ROWS_ * C_ / 4;       // 1048576
    const int n4a = C_ * C3_ / 4;         // 786432
    const int n4p = C_ * C_ / 4;          // 262144
    const int n4  = n4x + n4a + n4p;
    convert_all_kernel<<<(n4 + 255) / 256, 256>>>(
        (const float4*)x, (uint2*)xh,
        (const float4*)w_attn, (uint2*)wah,
        (const float4*)w_proj, (uint2*)wph,
        n4x, n4a, n4p);

    gemm_f16<true><<<dim3(C3_ / BN, ROWS_ / BM), 128, GEMM_SMEM>>>(xh, wah, qkv, ROWS_, C3_, C_);
    attn_kernel<<<dim3(T_ / 128, B_ * NH_), 256, ATT_SMEM>>>(qkv, y);
    gemm_f16<false><<<dim3(C_ / BN, ROWS_ / BM), 128, GEMM_SMEM>>>(y, wph, out, ROWS_, C_, C_);
}

// round 10
// speedup vs baseline: 2.8517x; 1.1018x over previous
#include <cuda_runtime.h>
#include <cuda_fp16.h>
#include <cstdint>
#include <cstddef>

#define B_   2
#define T_   2048
#define C_   1024
#define NH_  16
#define HD_  64
#define C3_  3072
#define ROWS_ 4096

// ---------------------------------------------------------------------------
// Scratch (__device__ globals; allocation-free rule). All intermediates fp16.
// ---------------------------------------------------------------------------
__device__ __half g_qkv[(size_t)ROWS_ * C3_];   // 24 MB
__device__ __half g_y[(size_t)ROWS_ * C_];      //  8 MB
__device__ __half g_xh[(size_t)ROWS_ * C_];     //  8 MB  x -> half
__device__ __half g_wah[(size_t)C_ * C3_];      //  6 MB  w_attn -> half
__device__ __half g_wph[(size_t)C_ * C_];       //  2 MB  w_proj -> half

// ---------------------------------------------------------------------------
// Helpers (sm_80-era ISA only; harness ptxas target lacks the 'a' suffix)
// ---------------------------------------------------------------------------
__device__ __forceinline__ void cp_async16(void* smem_dst, const void* gsrc) {
    uint32_t s = (uint32_t)__cvta_generic_to_shared(smem_dst);
    asm volatile("cp.async.cg.shared.global [%0], [%1], 16;\n" :: "r"(s), "l"(gsrc));
}
#define CP_COMMIT asm volatile("cp.async.commit_group;\n" ::: "memory")
#define CP_WAIT_1 asm volatile("cp.async.wait_group 1;\n" ::: "memory")
#define CP_WAIT_0 asm volatile("cp.async.wait_group 0;\n" ::: "memory")

// SW128 swizzle on byte offsets within a tile of 128-byte rows
#define SWZ128(off) ((off) ^ (((off) >> 3) & 0x70))

__device__ __forceinline__ void ldsm4(uint32_t r[4], uint32_t addr) {
    asm volatile("ldmatrix.sync.aligned.m8n8.x4.shared.b16 {%0,%1,%2,%3}, [%4];"
        : "=r"(r[0]), "=r"(r[1]), "=r"(r[2]), "=r"(r[3]) : "r"(addr));
}
__device__ __forceinline__ void ldsm4t(uint32_t& r0, uint32_t& r1, uint32_t& r2, uint32_t& r3,
                                       uint32_t addr) {
    asm volatile("ldmatrix.sync.aligned.m8n8.x4.trans.shared.b16 {%0,%1,%2,%3}, [%4];"
        : "=r"(r0), "=r"(r1), "=r"(r2), "=r"(r3) : "r"(addr));
}

__device__ __forceinline__ void mma_f16(float d[4], const uint32_t a[4], const uint32_t b[2]) {
    asm volatile(
        "mma.sync.aligned.m16n8k16.row.col.f32.f16.f16.f32 "
        "{%0,%1,%2,%3}, {%4,%5,%6,%7}, {%8,%9}, {%0,%1,%2,%3};\n"
        : "+f"(d[0]), "+f"(d[1]), "+f"(d[2]), "+f"(d[3])
        : "r"(a[0]), "r"(a[1]), "r"(a[2]), "r"(a[3]), "r"(b[0]), "r"(b[1]));
}

__device__ __forceinline__ float ex2f(float x) {
    float y;
    asm("ex2.approx.ftz.f32 %0, %1;" : "=f"(y) : "f"(x));
    return y;
}

// pack two floats to f16x2: lo -> low half, hi -> high half
__device__ __forceinline__ uint32_t pack_h2(float lo, float hi) {
    uint32_t u;
    asm("cvt.rn.f16x2.f32 %0, %1, %2;" : "=r"(u) : "f"(hi), "f"(lo));
    return u;
}

// ---------------------------------------------------------------------------
// Fused fp32 -> fp16 convert for x, w_attn, w_proj in one launch
// ---------------------------------------------------------------------------
__global__ void convert_all_kernel(const float4* __restrict__ x,  uint2* __restrict__ xh,
                                   const float4* __restrict__ wa, uint2* __restrict__ wah,
                                   const float4* __restrict__ wp, uint2* __restrict__ wph,
                                   int n4x, int n4a, int n4p)
{
    int i = blockIdx.x * 256 + threadIdx.x;
    const float4* src;
    uint2* dst;
    int j;
    if (i < n4x)            { src = x;  dst = xh;  j = i; }
    else if (i < n4x + n4a) { src = wa; dst = wah; j = i - n4x; }
    else if (i < n4x + n4a + n4p) { src = wp; dst = wph; j = i - n4x - n4a; }
    else return;
    float4 v = src[j];
    __half2 a = __floats2half2_rn(v.x, v.y);
    __half2 b = __floats2half2_rn(v.z, v.w);
    dst[j] = make_uint2(*(uint32_t*)&a, *(uint32_t*)&b);
}

// ---------------------------------------------------------------------------
// fp16 GEMM: C[M,N] = A[M,K] * B[K,N]  (A,B half; C half or float)
// Block 128x128x64, 128 threads, warp grid 2x2, warp tile 64x64.
// ldmatrix + m16n8k16, swizzled smem, THREE-stage cp.async pipeline:
// loads run two iterations ahead; wait_group 1 keeps one load in flight.
// ---------------------------------------------------------------------------
#define BM 128
#define BN 128
#define BK 64
#define A_ST_BYTES (BM * 128)                 // rows of 64 halves = 128 B
#define B_ST_BYTES (BK * 256)                 // rows of 128 halves = 256 B
#define STG_BYTES (A_ST_BYTES + B_ST_BYTES)   // 32768
#define GEMM_SMEM (3 * STG_BYTES)             // 98304 (2 CTAs/SM: 192 KB)

template<bool OUT_HALF>
__global__ __launch_bounds__(128, 2)
void gemm_f16(const __half* __restrict__ A, const __half* __restrict__ Bm,
              void* __restrict__ Cv, int M, int N, int K)
{
    extern __shared__ char smc[];
    const uint32_t sbase = (uint32_t)__cvta_generic_to_shared(smc);
    const int tid  = threadIdx.x;
    const int lane = tid & 31;
    const int warp = tid >> 5;        // 0..3
    const int wm   = warp & 1;
    const int wn   = warp >> 1;
    const int g    = lane >> 2;
    const int tg   = lane & 3;
    const int bm   = blockIdx.y * BM;
    const int bn   = blockIdx.x * BN;

    float acc[4][8][4];
    #pragma unroll
    for (int i = 0; i < 4; i++)
        #pragma unroll
        for (int j = 0; j < 8; j++)
            #pragma unroll
            for (int k = 0; k < 4; k++) acc[i][j][k] = 0.f;

    auto load_stage = [&](int kt, int s) {
        char* As = smc + s * STG_BYTES;
        char* Bs = As + A_ST_BYTES;
        #pragma unroll
        for (int p = 0; p < 8; p++) {        // A: 128 rows x 8 chunks of 16B
            int idx = tid + p * 128;
            int r = idx >> 3, c = idx & 7;
            cp_async16(As + SWZ128(r * 128 + c * 16),
                       A + (size_t)(bm + r) * K + kt * BK + c * 8);
        }
        #pragma unroll
        for (int p = 0; p < 8; p++) {        // B: 64 rows x 16 chunks (256B rows)
            int idx = tid + p * 128;
            int r = idx >> 4, c = idx & 15;
            cp_async16(Bs + r * 256 + ((c ^ (r & 7)) * 16),
                       Bm + (size_t)(kt * BK + r) * N + bn + c * 8);
        }
    };

    const int nk = K / BK;
    load_stage(0, 0); CP_COMMIT;
    load_stage(1, 1); CP_COMMIT;
    CP_WAIT_1;            // stage 0 landed; stage 1 in flight
    __syncthreads();

    for (int kt = 0; kt < nk; kt++) {
        const int cur = kt % 3;
        if (kt + 2 < nk) { load_stage(kt + 2, (kt + 2) % 3); CP_COMMIT; }

        const uint32_t aS = sbase + cur * STG_BYTES;
        const uint32_t bS = aS + A_ST_BYTES;

        #pragma unroll
        for (int ks = 0; ks < 4; ks++) {
            uint32_t af[4][4];
            #pragma unroll
            for (int mt = 0; mt < 4; mt++) {
                const int row = wm * 64 + mt * 16 + (lane & 15);
                const int ch  = ks * 2 + (lane >> 4);
                ldsm4(af[mt], aS + SWZ128(row * 128 + ch * 16));
            }
            uint32_t bf[8][2];
            #pragma unroll
            for (int pr = 0; pr < 4; pr++) {
                const int row = ks * 16 + (lane & 7) + (lane & 8);
                const int ch  = wn * 8 + pr * 2 + (lane >> 4);
                uint32_t r0, r1, r2, r3;
                ldsm4t(r0, r1, r2, r3, bS + row * 256 + ((ch ^ (row & 7)) * 16));
                bf[pr * 2][0] = r0;     bf[pr * 2][1] = r1;
                bf[pr * 2 + 1][0] = r2; bf[pr * 2 + 1][1] = r3;
            }
            #pragma unroll
            for (int mt = 0; mt < 4; mt++)
                #pragma unroll
                for (int nt = 0; nt < 8; nt++)
                    mma_f16(acc[mt][nt], af[mt], bf[nt]);
        }

        if (kt + 1 < nk) {
            if (kt + 2 < nk) { CP_WAIT_1; } else { CP_WAIT_0; }
            __syncthreads();
        }
    }

    // Epilogue: c0,c1 -> (row g, cols 2tg,2tg+1); c2,c3 -> row g+8
    #pragma unroll
    for (int mt = 0; mt < 4; mt++) {
        const int r0 = bm + wm * 64 + mt * 16 + g;
        #pragma unroll
        for (int nt = 0; nt < 8; nt++) {
            const int cc = bn + wn * 64 + nt * 8 + 2 * tg;
            if (OUT_HALF) {
                __half* Ch = (__half*)Cv;
                *(__half2*)&Ch[(size_t)r0 * N + cc]       = __floats2half2_rn(acc[mt][nt][0], acc[mt][nt][1]);
                *(__half2*)&Ch[(size_t)(r0 + 8) * N + cc] = __floats2half2_rn(acc[mt][nt][2], acc[mt][nt][3]);
            } else {
                float* Cf = (float*)Cv;
                *(float2*)&Cf[(size_t)r0 * N + cc]       = make_float2(acc[mt][nt][0], acc[mt][nt][1]);
                *(float2*)&Cf[(size_t)(r0 + 8) * N + cc] = make_float2(acc[mt][nt][2], acc[mt][nt][3]);
            }
        }
    }
}

// ---------------------------------------------------------------------------
// Flash attention, fp16 MMA, P in registers.
// One block per (q-tile of 64, b*h): 128 threads, 4 warps x 16 q-rows.
// KV tile 128 (halves softmax bookkeeping + barrier count per kv element).
// smem: Q[0,8K) K[8K,40K) x2(16K) V[40K,72K) x2(16K)   = 73728 B, 2 CTAs/SM.
// ---------------------------------------------------------------------------
#define Q_OFF 0
#define K_OFF 8192
#define V_OFF 40960
#define KV_STG 16384
#define ATT_SMEM 73728

__global__ __launch_bounds__(128, 2)
void attn_kernel(const __half* __restrict__ qkv, __half* __restrict__ y)
{
    extern __shared__ char smc[];
    const uint32_t sbase = (uint32_t)__cvta_generic_to_shared(smc);
    const int tid  = threadIdx.x;
    const int lane = tid & 31;
    const int warp = tid >> 5;        // 0..3
    const int g    = lane >> 2;
    const int tg   = lane & 3;

    const int qt = gridDim.x - 1 - blockIdx.x;   // heavy tiles first (0..31)
    const int bh = blockIdx.y;
    const int b  = bh >> 4;
    const int h  = bh & 15;

    const __half* base = qkv + (size_t)b * T_ * C3_;
    const int qcol = h * HD_;
    const int kcol = C_ + h * HD_;
    const int vcol = 2 * C_ + h * HD_;

    // Q tile 64x64 halves -> smem (swizzled), once
    #pragma unroll
    for (int p = 0; p < 4; p++) {
        int idx = tid + p * 128;
        int r = idx >> 3, c = idx & 7;
        cp_async16(smc + Q_OFF + SWZ128(r * 128 + c * 16),
                   base + (size_t)(qt * 64 + r) * C3_ + qcol + c * 8);
    }

    auto load_kv = [&](int j, int s) {
        #pragma unroll
        for (int p = 0; p < 8; p++) {          // 128 rows x 8 chunks each
            int idx = tid + p * 128;
            int r = idx >> 3, c = idx & 7;
            const size_t grow = (size_t)(j * 128 + r) * C3_;
            const int so = SWZ128(r * 128 + c * 16);
            cp_async16(smc + K_OFF + s * KV_STG + so, base + grow + kcol + c * 8);
            cp_async16(smc + V_OFF + s * KV_STG + so, base + grow + vcol + c * 8);
        }
    };

    load_kv(0, 0); CP_COMMIT;
    CP_WAIT_0; __syncthreads();

    // Q a-frags, held in registers for the whole kv loop
    uint32_t qf[4][4];
    #pragma unroll
    for (int ks = 0; ks < 4; ks++) {
        const int row = warp * 16 + (lane & 15);
        const int ch  = ks * 2 + (lane >> 4);
        ldsm4(qf[ks], sbase + Q_OFF + SWZ128(row * 128 + ch * 16));
    }

    float o[8][4];
    #pragma unroll
    for (int i = 0; i < 8; i++)
        #pragma unroll
        for (int jj = 0; jj < 4; jj++) o[i][jj] = 0.f;
    float m0 = -INFINITY, m1 = -INFINITY, l0 = 0.f, l1 = 0.f;

    const float SC = 0.125f * 1.4426950408889634f;   // 1/sqrt(64) * log2(e)

    const int jend = (qt * 64 + 63) >> 7;   // last kv-128 tile needed
    for (int j = 0; j <= jend; j++) {
        const int cur = j & 1;
        if (j < jend) { load_kv(j + 1, cur ^ 1); CP_COMMIT; }

        const uint32_t kS = sbase + K_OFF + cur * KV_STG;
        const uint32_t vS = sbase + V_OFF + cur * KV_STG;

        // S = Q @ K^T   (16 q-rows x 128 kv per warp)
        float s[16][4];
        #pragma unroll
        for (int nt = 0; nt < 16; nt++)
            #pragma unroll
            for (int k4 = 0; k4 < 4; k4++) s[nt][k4] = 0.f;

        #pragma unroll
        for (int ks = 0; ks < 4; ks++) {
            uint32_t bf[16][2];
            #pragma unroll
            for (int pr = 0; pr < 8; pr++) {
                const int row = pr * 16 + (lane & 7) + ((lane >> 4) << 3);
                const int ch  = ks * 2 + ((lane >> 3) & 1);
                uint32_t rr[4];
                ldsm4(rr, kS + SWZ128(row * 128 + ch * 16));
                bf[pr * 2][0] = rr[0];     bf[pr * 2][1] = rr[1];
                bf[pr * 2 + 1][0] = rr[2]; bf[pr * 2 + 1][1] = rr[3];
            }
            #pragma unroll
            for (int nt = 0; nt < 16; nt++)
                mma_f16(s[nt], qf[ks], bf[nt]);
        }

        // scale
        #pragma unroll
        for (int nt = 0; nt < 16; nt++) {
            s[nt][0] *= SC; s[nt][1] *= SC; s[nt][2] *= SC; s[nt][3] *= SC;
        }

        // causal mask (only the last tile can straddle the diagonal)
        if (j == jend) {
            const int rg0 = qt * 64 + warp * 16 + g;
            const int rg1 = rg0 + 8;
            #pragma unroll
            for (int nt = 0; nt < 16; nt++) {
                const int c0 = j * 128 + nt * 8 + 2 * tg;
                if (c0     > rg0) s[nt][0] = -1e30f;
                if (c0 + 1 > rg0) s[nt][1] = -1e30f;
                if (c0     > rg1) s[nt][2] = -1e30f;
                if (c0 + 1 > rg1) s[nt][3] = -1e30f;
            }
        }

        // online softmax, base-2 (row g -> s[.][0,1]; row g+8 -> s[.][2,3])
        float mt0 = -INFINITY, mt1 = -INFINITY;
        #pragma unroll
        for (int nt = 0; nt < 16; nt++) {
            mt0 = fmaxf(mt0, fmaxf(s[nt][0], s[nt][1]));
            mt1 = fmaxf(mt1, fmaxf(s[nt][2], s[nt][3]));
        }
        mt0 = fmaxf(mt0, __shfl_xor_sync(0xffffffffu, mt0, 1));
        mt0 = fmaxf(mt0, __shfl_xor_sync(0xffffffffu, mt0, 2));
        mt1 = fmaxf(mt1, __shfl_xor_sync(0xffffffffu, mt1, 1));
        mt1 = fmaxf(mt1, __shfl_xor_sync(0xffffffffu, mt1, 2));

        const float mn0 = fmaxf(m0, mt0), mn1 = fmaxf(m1, mt1);
        const float f0 = ex2f(m0 - mn0), f1 = ex2f(m1 - mn1);

        // exp + pack P directly into a-frags (c-frag layout == a-frag layout)
        uint32_t pf[8][4];
        float ls0 = 0.f, ls1 = 0.f;
        #pragma unroll
        for (int ks = 0; ks < 8; ks++) {
            const float pa0 = ex2f(s[2*ks][0] - mn0);
            const float pa1 = ex2f(s[2*ks][1] - mn0);
            const float pa2 = ex2f(s[2*ks][2] - mn1);
            const float pa3 = ex2f(s[2*ks][3] - mn1);
            const float pb0 = ex2f(s[2*ks+1][0] - mn0);
            const float pb1 = ex2f(s[2*ks+1][1] - mn0);
            const float pb2 = ex2f(s[2*ks+1][2] - mn1);
            const float pb3 = ex2f(s[2*ks+1][3] - mn1);
            ls0 += pa0 + pa1 + pb0 + pb1;
            ls1 += pa2 + pa3 + pb2 + pb3;
            pf[ks][0] = pack_h2(pa0, pa1);
            pf[ks][1] = pack_h2(pa2, pa3);
            pf[ks][2] = pack_h2(pb0, pb1);
            pf[ks][3] = pack_h2(pb2, pb3);
        }
        ls0 += __shfl_xor_sync(0xffffffffu, ls0, 1);
        ls0 += __shfl_xor_sync(0xffffffffu, ls0, 2);
        ls1 += __shfl_xor_sync(0xffffffffu, ls1, 1);
        ls1 += __shfl_xor_sync(0xffffffffu, ls1, 2);

        l0 = l0 * f0 + ls0;
        l1 = l1 * f1 + ls1;
        m0 = mn0; m1 = mn1;

        #pragma unroll
        for (int nt = 0; nt < 8; nt++) {
            o[nt][0] *= f0; o[nt][1] *= f0;
            o[nt][2] *= f1; o[nt][3] *= f1;
        }

        // O += P @ V   (P a-frags in registers; V b-frags via ldmatrix.trans)
        #pragma unroll
        for (int ks = 0; ks < 8; ks++) {
            uint32_t bf[8][2];
            #pragma unroll
            for (int pr = 0; pr < 4; pr++) {
                const int row = ks * 16 + (lane & 15);
                const int ch  = pr * 2 + (lane >> 4);
                uint32_t r0, r1, r2, r3;
                ldsm4t(r0, r1, r2, r3, vS + SWZ128(row * 128 + ch * 16));
                bf[pr * 2][0] = r0;     bf[pr * 2][1] = r1;
                bf[pr * 2 + 1][0] = r2; bf[pr * 2 + 1][1] = r3;
            }
            #pragma unroll
            for (int nt = 0; nt < 8; nt++)
                mma_f16(o[nt], pf[ks], bf[nt]);
        }

        if (j < jend) { CP_WAIT_0; __syncthreads(); }
    }

    // normalize + write y (half)
    const float i0 = 1.f / l0, i1 = 1.f / l1;
    const int r0 = b * T_ + qt * 64 + warp * 16 + g;
    #pragma unroll
    for (int nt = 0; nt < 8; nt++) {
        const int c = h * HD_ + nt * 8 + 2 * tg;
        *(__half2*)&y[(size_t)r0 * C_ + c] =
            __floats2half2_rn(o[nt][0] * i0, o[nt][1] * i0);
        *(__half2*)&y[(size_t)(r0 + 8) * C_ + c] =
            __floats2half2_rn(o[nt][2] * i1, o[nt][3] * i1);
    }
}

// ---------------------------------------------------------------------------
// Launch chain: convert -> qkv GEMM -> attention -> proj GEMM
// ---------------------------------------------------------------------------
extern "C" void kernel_launch(void* const* d_in, const int* in_sizes, int n_in,
                              void* d_out, int out_size)
{
    (void)in_sizes; (void)n_in; (void)out_size;
    const float* x      = (const float*)d_in[0];
    const float* w_attn = (const float*)d_in[1];
    const float* w_proj = (const float*)d_in[2];
    float* out = (float*)d_out;

    __half *qkv, *y, *xh, *wah, *wph;
    cudaGetSymbolAddress((void**)&qkv, g_qkv);
    cudaGetSymbolAddress((void**)&y,   g_y);
    cudaGetSymbolAddress((void**)&xh,  g_xh);
    cudaGetSymbolAddress((void**)&wah, g_wah);
    cudaGetSymbolAddress((void**)&wph, g_wph);

    cudaFuncSetAttribute(gemm_f16<true>,  cudaFuncAttributeMaxDynamicSharedMemorySize, GEMM_SMEM);
    cudaFuncSetAttribute(gemm_f16<false>, cudaFuncAttributeMaxDynamicSharedMemorySize, GEMM_SMEM);
    cudaFuncSetAttribute(attn_kernel,     cudaFuncAttributeMaxDynamicSharedMemorySize, ATT_SMEM);

    const int n4x = ROWS_ * C_ / 4;       // 1048576
    const int n4a = C_ * C3_ / 4;         // 786432
    const int n4p = C_ * C_ / 4;          // 262144
    const int n4  = n4x + n4a + n4p;
    convert_all_kernel<<<(n4 + 255) / 256, 256>>>(
        (const float4*)x, (uint2*)xh,
        (const float4*)w_attn, (uint2*)wah,
        (const float4*)w_proj, (uint2*)wph,
        n4x, n4a, n4p);

    gemm_f16<true><<<dim3(C3_ / BN, ROWS_ / BM), 128, GEMM_SMEM>>>(xh, wah, qkv, ROWS_, C3_, C_);
    attn_kernel<<<dim3(T_ / 64, B_ * NH_), 128, ATT_SMEM>>>(qkv, y);
    gemm_f16<false><<<dim3(C_ / BN, ROWS_ / BM), 128, GEMM_SMEM>>>(y, wph, out, ROWS_, C_, C_);
}